// round 2
// baseline (speedup 1.0000x reference)
#include <cuda_runtime.h>
#include <math.h>

#define H   1024
#define ID  512
#define NE  32
#define TK  4
#define MAXT 4096
#define MAXN (MAXT*TK)
#define RSCALE 2.5f

// ---------------- scratch (device globals; referenced ONLY in device code) --
__device__ float g_act[(size_t)MAXN * ID];     // routed silu(g)*u, sorted rows
__device__ float g_outs[(size_t)MAXN * H];     // routed down output, sorted rows
__device__ float g_shact[(size_t)MAXT * ID];   // shared expert intermediate
__device__ float g_shout[(size_t)MAXT * H];    // shared expert output
__device__ float g_tw[MAXT * TK];              // routing weights
__device__ int   g_topk[MAXT * TK];            // routed expert ids per slot
__device__ int   g_counts[NE];
__device__ int   g_offsets[NE + 1];
__device__ int   g_cursor[NE];
__device__ int   g_rowmap[MAXN];               // sorted pos -> slot (t*TK+k)
__device__ int   g_pos[MAXN];                  // slot -> sorted pos

// ---------------- init --------------------------------------------------
__global__ void init_kernel() {
    int i = threadIdx.x;
    if (i < NE) { g_counts[i] = 0; g_cursor[i] = 0; }
}

// ---------------- gate + routing (1 token per block, 128 threads) -------
__global__ void __launch_bounds__(128)
gate_kernel(const float* __restrict__ X, const float* __restrict__ GW,
            const float* __restrict__ EB,
            float* outLogits, float* outTopkF)
{
    __shared__ __align__(16) float xs[H];
    __shared__ float sl[NE];
    __shared__ float ssc[NE];
    __shared__ float ssrt[NE];

    int t = blockIdx.x;
    const float* x = X + (size_t)t * H;
    for (int c = threadIdx.x; c < H; c += 128) xs[c] = x[c];
    __syncthreads();

    // 4 threads per expert, 256 elements each
    int e = threadIdx.x >> 2, q = threadIdx.x & 3;
    const float* w = GW + (size_t)e * H;
    float s = 0.f;
    int c0 = q * 256;
    #pragma unroll 8
    for (int c = c0; c < c0 + 256; c += 4) {
        float4 xv = *(const float4*)&xs[c];
        float4 wv = *(const float4*)(w + c);
        s += xv.x * wv.x + xv.y * wv.y + xv.z * wv.z + xv.w * wv.w;
    }
    s += __shfl_down_sync(0xffffffffu, s, 2);
    s += __shfl_down_sync(0xffffffffu, s, 1);
    if (q == 0) {
        sl[e] = s;
        if (outLogits) outLogits[(size_t)t * NE + e] = s;
    }
    __syncthreads();

    if (threadIdx.x < NE) {
        float v = sl[threadIdx.x];
        float sc = 1.f / (1.f + expf(-v));
        ssc[threadIdx.x] = sc;
        ssrt[threadIdx.x] = sc + EB[threadIdx.x];
    }
    __syncthreads();

    if (threadIdx.x == 0) {
        // group scores = sum of top-2 within each group of 8
        float gs[4];
        #pragma unroll
        for (int g = 0; g < 4; g++) {
            float m1 = -1e30f, m2 = -1e30f;
            #pragma unroll
            for (int j = 0; j < 8; j++) {
                float v = ssrt[g * 8 + j];
                if (v > m1) { m2 = m1; m1 = v; }
                else if (v > m2) { m2 = v; }
            }
            gs[g] = m1 + m2;
        }
        // top-2 groups (ties -> lower index, like lax.top_k)
        int g1 = 0;
        for (int g = 1; g < 4; g++) if (gs[g] > gs[g1]) g1 = g;
        int g2 = -1;
        for (int g = 0; g < 4; g++) {
            if (g == g1) continue;
            if (g2 < 0 || gs[g] > gs[g2]) g2 = g;
        }
        // top-4 experts among allowed groups (descending, ties -> lower idx)
        bool used[NE];
        #pragma unroll
        for (int i = 0; i < NE; i++) used[i] = false;
        int idx[TK]; float wts[TK]; float sum = 0.f;
        #pragma unroll
        for (int k = 0; k < TK; k++) {
            int best = -1; float bv = -1e30f;
            for (int i = 0; i < NE; i++) {
                int grp = i >> 3;
                if (grp != g1 && grp != g2) continue;
                if (used[i]) continue;
                if (ssrt[i] > bv) { bv = ssrt[i]; best = i; }
            }
            used[best] = true;
            idx[k] = best;
            wts[k] = ssc[best];
            sum += wts[k];
        }
        float inv = RSCALE / (sum + 1e-20f);
        #pragma unroll
        for (int k = 0; k < TK; k++) {
            g_topk[t * TK + k] = idx[k];
            g_tw[t * TK + k]   = wts[k] * inv;
            if (outTopkF) outTopkF[t * TK + k] = (float)idx[k];
            atomicAdd(&g_counts[idx[k]], 1);
        }
    }
}

// ---------------- scan offsets ------------------------------------------
__global__ void scan_kernel() {
    if (threadIdx.x == 0) {
        int o = 0;
        for (int e = 0; e < NE; e++) { g_offsets[e] = o; o += g_counts[e]; }
        g_offsets[NE] = o;
    }
}

// ---------------- scatter to expert-sorted order ------------------------
__global__ void scatter_kernel(int N) {
    int s = blockIdx.x * 256 + threadIdx.x;
    if (s >= N) return;
    int e = g_topk[s];
    int p = g_offsets[e] + atomicAdd(&g_cursor[e], 1);
    g_rowmap[p] = s;
    g_pos[s] = p;
}

// ---------------- fused gate+up GEMM with SiLU epilogue ------------------
// shared_mode=0: rows via g_rowmap/g_offsets, out g_act.
// shared_mode=1: rows 0..rowsShared-1 direct, out g_shact, expert 0 only.
__global__ void __launch_bounds__(256)
gemm_gateup(const float* __restrict__ X,
            const float* __restrict__ Wg, const float* __restrict__ Wu,
            int shared_mode, int rowsShared)
{
    __shared__ __align__(16) float As[64][16];
    __shared__ __align__(16) float Bgs[16][64];
    __shared__ __align__(16) float Bus[16][64];
    __shared__ int tok[64];

    float* __restrict__ Act = shared_mode ? g_shact : g_act;

    int e = blockIdx.z;
    int r0, cnt;
    if (shared_mode) { r0 = 0; cnt = rowsShared; }
    else             { r0 = g_offsets[e]; cnt = g_offsets[e + 1] - r0; }
    int mbase = blockIdx.y * 64;
    if (mbase >= cnt) return;
    int n0 = blockIdx.x * 64;

    const float* wg = Wg + (size_t)e * H * ID;
    const float* wu = Wu + (size_t)e * H * ID;

    int tid = threadIdx.x;
    if (tid < 64) {
        int rr = mbase + tid;
        int tt = -1;
        if (rr < cnt) tt = shared_mode ? (r0 + rr) : (g_rowmap[r0 + rr] >> 2);
        tok[tid] = tt;
    }
    __syncthreads();

    int tx = tid & 15, ty = tid >> 4;
    float accG[4][4] = {{0}}, accU[4][4] = {{0}};

    int la_r = tid >> 2,  la_k = (tid & 3) << 2;   // A: 64 rows x 4 f4
    int lb_k = tid >> 4,  lb_n = (tid & 15) << 2;  // B: 16 rows x 16 f4

    for (int k0 = 0; k0 < H; k0 += 16) {
        float4 av = make_float4(0.f, 0.f, 0.f, 0.f);
        int tt = tok[la_r];
        if (tt >= 0) av = *(const float4*)(X + (size_t)tt * H + k0 + la_k);
        *(float4*)&As[la_r][la_k] = av;
        *(float4*)&Bgs[lb_k][lb_n] = *(const float4*)(wg + (size_t)(k0 + lb_k) * ID + n0 + lb_n);
        *(float4*)&Bus[lb_k][lb_n] = *(const float4*)(wu + (size_t)(k0 + lb_k) * ID + n0 + lb_n);
        __syncthreads();
        #pragma unroll
        for (int kk = 0; kk < 16; kk++) {
            float a[4];
            #pragma unroll
            for (int i = 0; i < 4; i++) a[i] = As[ty * 4 + i][kk];
            float4 bg = *(const float4*)&Bgs[kk][tx * 4];
            float4 bu = *(const float4*)&Bus[kk][tx * 4];
            #pragma unroll
            for (int i = 0; i < 4; i++) {
                accG[i][0] += a[i] * bg.x; accG[i][1] += a[i] * bg.y;
                accG[i][2] += a[i] * bg.z; accG[i][3] += a[i] * bg.w;
                accU[i][0] += a[i] * bu.x; accU[i][1] += a[i] * bu.y;
                accU[i][2] += a[i] * bu.z; accU[i][3] += a[i] * bu.w;
            }
        }
        __syncthreads();
    }

    #pragma unroll
    for (int i = 0; i < 4; i++) {
        int rr = mbase + ty * 4 + i;
        if (rr >= cnt) continue;
        float4 o;
        float g, u;
        g = accG[i][0]; u = accU[i][0]; o.x = (g / (1.f + expf(-g))) * u;
        g = accG[i][1]; u = accU[i][1]; o.y = (g / (1.f + expf(-g))) * u;
        g = accG[i][2]; u = accU[i][2]; o.z = (g / (1.f + expf(-g))) * u;
        g = accG[i][3]; u = accU[i][3]; o.w = (g / (1.f + expf(-g))) * u;
        *(float4*)(Act + (size_t)(r0 + rr) * ID + n0 + tx * 4) = o;
    }
}

// ---------------- down GEMM ----------------------------------------------
// shared_mode=0: A=g_act, Out=g_outs, rows via g_offsets.
// shared_mode=1: A=g_shact, Out=g_shout, rows 0..rowsShared-1.
__global__ void __launch_bounds__(256)
gemm_down(const float* __restrict__ W, int shared_mode, int rowsShared)
{
    __shared__ __align__(16) float As[64][16];
    __shared__ __align__(16) float Bs[16][64];

    const float* __restrict__ A  = shared_mode ? g_shact : g_act;
    float* __restrict__ Out      = shared_mode ? g_shout : g_outs;

    int e = blockIdx.z;
    int r0, cnt;
    if (shared_mode) { r0 = 0; cnt = rowsShared; }
    else             { r0 = g_offsets[e]; cnt = g_offsets[e + 1] - r0; }
    int mbase = blockIdx.y * 64;
    if (mbase >= cnt) return;
    int n0 = blockIdx.x * 64;

    const float* wd = W + (size_t)e * ID * H;

    int tid = threadIdx.x;
    int tx = tid & 15, ty = tid >> 4;
    float acc[4][4] = {{0}};

    int la_r = tid >> 2,  la_k = (tid & 3) << 2;
    int lb_k = tid >> 4,  lb_n = (tid & 15) << 2;

    for (int k0 = 0; k0 < ID; k0 += 16) {
        float4 av = make_float4(0.f, 0.f, 0.f, 0.f);
        int rr = mbase + la_r;
        if (rr < cnt) av = *(const float4*)(A + (size_t)(r0 + rr) * ID + k0 + la_k);
        *(float4*)&As[la_r][la_k] = av;
        *(float4*)&Bs[lb_k][lb_n] = *(const float4*)(wd + (size_t)(k0 + lb_k) * H + n0 + lb_n);
        __syncthreads();
        #pragma unroll
        for (int kk = 0; kk < 16; kk++) {
            float a[4];
            #pragma unroll
            for (int i = 0; i < 4; i++) a[i] = As[ty * 4 + i][kk];
            float4 b = *(const float4*)&Bs[kk][tx * 4];
            #pragma unroll
            for (int i = 0; i < 4; i++) {
                acc[i][0] += a[i] * b.x; acc[i][1] += a[i] * b.y;
                acc[i][2] += a[i] * b.z; acc[i][3] += a[i] * b.w;
            }
        }
        __syncthreads();
    }

    #pragma unroll
    for (int i = 0; i < 4; i++) {
        int rr = mbase + ty * 4 + i;
        if (rr >= cnt) continue;
        float4 o = make_float4(acc[i][0], acc[i][1], acc[i][2], acc[i][3]);
        *(float4*)(Out + (size_t)(r0 + rr) * H + n0 + tx * 4) = o;
    }
}

// ---------------- combine: y = shared + sum_k tw * routed -----------------
__global__ void __launch_bounds__(256)
combine_kernel(float* __restrict__ Y)
{
    int t = blockIdx.x;
    __shared__ float w[TK];
    __shared__ int   p[TK];
    if (threadIdx.x < TK) {
        w[threadIdx.x] = g_tw[t * TK + threadIdx.x];
        p[threadIdx.x] = g_pos[t * TK + threadIdx.x];
    }
    __syncthreads();
    int c = threadIdx.x * 4;
    float4 acc = *(const float4*)(g_shout + (size_t)t * H + c);
    #pragma unroll
    for (int k = 0; k < TK; k++) {
        float4 v = *(const float4*)(g_outs + (size_t)p[k] * H + c);
        acc.x += w[k] * v.x; acc.y += w[k] * v.y;
        acc.z += w[k] * v.z; acc.w += w[k] * v.w;
    }
    *(float4*)(Y + (size_t)t * H + c) = acc;
}

// ---------------- tail fill (defensive) -----------------------------------
__global__ void fill_zero(float* p, long long n) {
    long long i = (long long)blockIdx.x * 256 + threadIdx.x;
    if (i < n) p[i] = 0.f;
}

// ---------------- launch ---------------------------------------------------
extern "C" void kernel_launch(void* const* d_in, const int* in_sizes, int n_in,
                              void* d_out, int out_size)
{
    const float* x   = (const float*)d_in[0];
    const float* gw  = (const float*)d_in[1];
    const float* eb  = (const float*)d_in[2];
    const float* wg  = (const float*)d_in[3];
    const float* wu  = (const float*)d_in[4];
    const float* wd  = (const float*)d_in[5];
    const float* wsg = (const float*)d_in[6];
    const float* wsu = (const float*)d_in[7];
    const float* wsd = (const float*)d_in[8];
    float* out = (float*)d_out;

    int T = in_sizes[0] / H;     // 4096 tokens
    int N = T * TK;

    long long oL = (long long)T * H;
    long long oK = oL + (long long)T * NE;
    long long oEnd = oK + (long long)T * TK;

    float* outLogits = ((long long)out_size >= oK)   ? (out + oL) : nullptr;
    float* outTopkF  = ((long long)out_size >= oEnd) ? (out + oK) : nullptr;
    long long written = ((long long)out_size >= oEnd) ? oEnd
                       : ((long long)out_size >= oK) ? oK
                       : oL;

    init_kernel<<<1, 32>>>();
    gate_kernel<<<T, 128>>>(x, gw, eb, outLogits, outTopkF);
    scan_kernel<<<1, 1>>>();
    scatter_kernel<<<(N + 255) / 256, 256>>>(N);

    // routed experts (worst-case per-expert rows = T)
    gemm_gateup<<<dim3(ID / 64, T / 64, NE), 256>>>(x, wg, wu, 0, 0);
    gemm_down  <<<dim3(H / 64, T / 64, NE), 256>>>(wd, 0, 0);
    // shared expert (single group over all tokens)
    gemm_gateup<<<dim3(ID / 64, T / 64, 1), 256>>>(x, wsg, wsu, 1, T);
    gemm_down  <<<dim3(H / 64, T / 64, 1), 256>>>(wsd, 1, T);

    combine_kernel<<<T, 256>>>(out);

    if ((long long)out_size > written) {
        long long rest = (long long)out_size - written;
        fill_zero<<<(unsigned)((rest + 255) / 256), 256>>>(out + written, rest);
    }
}

// round 4
// speedup vs baseline: 1.6476x; 1.6476x over previous
#include <cuda_runtime.h>
#include <cuda_bf16.h>
#include <math.h>
#include <stdint.h>

#define H   1024
#define ID  512
#define NE  32
#define TK  4
#define MAXT 4096
#define MAXN (MAXT*TK)
#define RSCALE 2.5f

#define KCH   64
#define KPAD  72                       // elems per smem row; 144B, 9x16B -> conflict-free
#define PLANE (128*KPAD*2)             // 18432 B
#define STAGE (4*PLANE)                // Ahi,Alo,Bhi,Blo = 73728 B
#define SMEM_DYN (2*STAGE)             // 147456 B

// ---------------- scratch (device globals; referenced ONLY in device code) --
__device__ float g_g[(size_t)MAXN * ID];
__device__ float g_u[(size_t)MAXN * ID];
__device__ float g_act[(size_t)MAXN * ID];
__device__ float g_outs[(size_t)MAXN * H];
__device__ float g_shg[(size_t)MAXT * ID];
__device__ float g_shu[(size_t)MAXT * ID];
__device__ float g_shact[(size_t)MAXT * ID];
__device__ float g_shout[(size_t)MAXT * H];
__device__ float g_tw[MAXT * TK];
__device__ int   g_topk[MAXT * TK];
__device__ int   g_counts[NE];
__device__ int   g_offsets[NE + 1];
__device__ int   g_cursor[NE];
__device__ int   g_rowmap[MAXN];
__device__ int   g_pos[MAXN];

// prepped weights: per expert: hi plane [N][K] bf16, then lo plane [N][K]
__device__ __nv_bfloat16 g_pwg[(size_t)NE*2*ID*H];
__device__ __nv_bfloat16 g_pwu[(size_t)NE*2*ID*H];
__device__ __nv_bfloat16 g_pwd[(size_t)NE*2*H*ID];
__device__ __nv_bfloat16 g_psg[(size_t)2*ID*H];
__device__ __nv_bfloat16 g_psu[(size_t)2*ID*H];
__device__ __nv_bfloat16 g_psd[(size_t)2*H*ID];

// ---------------- helpers ----------------------------------------------
__device__ __forceinline__ uint32_t smem_u32(const void* p) {
    return (uint32_t)__cvta_generic_to_shared(p);
}
__device__ __forceinline__ void split2(float v0, float v1, uint32_t& hi, uint32_t& lo) {
    __nv_bfloat16 h0 = __float2bfloat16_rn(v0), h1 = __float2bfloat16_rn(v1);
    float r0 = v0 - __bfloat162float(h0), r1 = v1 - __bfloat162float(h1);
    __nv_bfloat16 l0 = __float2bfloat16_rn(r0), l1 = __float2bfloat16_rn(r1);
    hi = (uint32_t)(*(uint16_t*)&h0) | ((uint32_t)(*(uint16_t*)&h1) << 16);
    lo = (uint32_t)(*(uint16_t*)&l0) | ((uint32_t)(*(uint16_t*)&l1) << 16);
}
__device__ __forceinline__ float silu(float g) { return g / (1.f + expf(-g)); }

#define LDMX4(r0_,r1_,r2_,r3_,addr) \
    asm volatile("ldmatrix.sync.aligned.m8n8.x4.shared.b16 {%0,%1,%2,%3}, [%4];" \
        : "=r"(r0_), "=r"(r1_), "=r"(r2_), "=r"(r3_) : "r"(addr))

#define MMA16816(c_, a_, b0_, b1_) \
    asm volatile("mma.sync.aligned.m16n8k16.row.col.f32.bf16.bf16.f32 " \
        "{%0,%1,%2,%3}, {%4,%5,%6,%7}, {%8,%9}, {%0,%1,%2,%3};" \
        : "+f"((c_)[0]), "+f"((c_)[1]), "+f"((c_)[2]), "+f"((c_)[3]) \
        : "r"((a_)[0]), "r"((a_)[1]), "r"((a_)[2]), "r"((a_)[3]), \
          "r"(b0_), "r"(b1_))

#define CP16(dst, src) \
    asm volatile("cp.async.cg.shared.global [%0], [%1], 16;" :: "r"(dst), "l"(src))

// ---------------- init / routing (proven in R2) --------------------------
__global__ void init_kernel() {
    int i = threadIdx.x;
    if (i < NE) { g_counts[i] = 0; g_cursor[i] = 0; }
}

__global__ void __launch_bounds__(128)
gate_kernel(const float* __restrict__ X, const float* __restrict__ GW,
            const float* __restrict__ EB,
            float* outLogits, float* outTopkF)
{
    __shared__ __align__(16) float xs[H];
    __shared__ float sl[NE];
    __shared__ float ssc[NE];
    __shared__ float ssrt[NE];

    int t = blockIdx.x;
    const float* x = X + (size_t)t * H;
    for (int c = threadIdx.x; c < H; c += 128) xs[c] = x[c];
    __syncthreads();

    int e = threadIdx.x >> 2, q = threadIdx.x & 3;
    const float* w = GW + (size_t)e * H;
    float s = 0.f;
    int c0 = q * 256;
    #pragma unroll 8
    for (int c = c0; c < c0 + 256; c += 4) {
        float4 xv = *(const float4*)&xs[c];
        float4 wv = *(const float4*)(w + c);
        s += xv.x * wv.x + xv.y * wv.y + xv.z * wv.z + xv.w * wv.w;
    }
    s += __shfl_down_sync(0xffffffffu, s, 2);
    s += __shfl_down_sync(0xffffffffu, s, 1);
    if (q == 0) {
        sl[e] = s;
        if (outLogits) outLogits[(size_t)t * NE + e] = s;
    }
    __syncthreads();

    if (threadIdx.x < NE) {
        float v = sl[threadIdx.x];
        float sc = 1.f / (1.f + expf(-v));
        ssc[threadIdx.x] = sc;
        ssrt[threadIdx.x] = sc + EB[threadIdx.x];
    }
    __syncthreads();

    if (threadIdx.x == 0) {
        float gs[4];
        #pragma unroll
        for (int g = 0; g < 4; g++) {
            float m1 = -1e30f, m2 = -1e30f;
            #pragma unroll
            for (int j = 0; j < 8; j++) {
                float v = ssrt[g * 8 + j];
                if (v > m1) { m2 = m1; m1 = v; }
                else if (v > m2) { m2 = v; }
            }
            gs[g] = m1 + m2;
        }
        int g1 = 0;
        for (int g = 1; g < 4; g++) if (gs[g] > gs[g1]) g1 = g;
        int g2 = -1;
        for (int g = 0; g < 4; g++) {
            if (g == g1) continue;
            if (g2 < 0 || gs[g] > gs[g2]) g2 = g;
        }
        bool used[NE];
        #pragma unroll
        for (int i = 0; i < NE; i++) used[i] = false;
        int idx[TK]; float wts[TK]; float sum = 0.f;
        #pragma unroll
        for (int k = 0; k < TK; k++) {
            int best = -1; float bv = -1e30f;
            for (int i = 0; i < NE; i++) {
                int grp = i >> 3;
                if (grp != g1 && grp != g2) continue;
                if (used[i]) continue;
                if (ssrt[i] > bv) { bv = ssrt[i]; best = i; }
            }
            used[best] = true;
            idx[k] = best;
            wts[k] = ssc[best];
            sum += wts[k];
        }
        float inv = RSCALE / (sum + 1e-20f);
        #pragma unroll
        for (int k = 0; k < TK; k++) {
            g_topk[t * TK + k] = idx[k];
            g_tw[t * TK + k]   = wts[k] * inv;
            if (outTopkF) outTopkF[t * TK + k] = (float)idx[k];
            atomicAdd(&g_counts[idx[k]], 1);
        }
    }
}

__global__ void scan_kernel() {
    if (threadIdx.x == 0) {
        int o = 0;
        for (int e = 0; e < NE; e++) { g_offsets[e] = o; o += g_counts[e]; }
        g_offsets[NE] = o;
    }
}

__global__ void scatter_kernel(int N) {
    int s = blockIdx.x * 256 + threadIdx.x;
    if (s >= N) return;
    int e = g_topk[s];
    int p = g_offsets[e] + atomicAdd(&g_cursor[e], 1);
    g_rowmap[p] = s;
    g_pos[s] = p;
}

// ---------------- weight prep: W[k][n] f32 -> [n][K] bf16 hi/lo planes ----
__global__ void __launch_bounds__(256)
prep_kernel(const float* __restrict__ W, int K, int N, int which)
{
    __shared__ float sT[128][65];
    int kc = blockIdx.x, nt = blockIdx.y, e = blockIdx.z;
    __nv_bfloat16* pB =
        which == 0 ? g_pwg : which == 1 ? g_pwu : which == 2 ? g_pwd :
        which == 3 ? g_psg : which == 4 ? g_psu : g_psd;
    size_t NK = (size_t)N * K;
    __nv_bfloat16* hiP = pB + (size_t)e * 2 * NK;
    __nv_bfloat16* loP = hiP + NK;
    const float* src = W + ((size_t)e * K + (size_t)kc * 64) * N + (size_t)nt * 128;

    int tid = threadIdx.x;
    for (int i = tid; i < 64 * 32; i += 256) {
        int k = i >> 5, nf = (i & 31) * 4;
        float4 v = *(const float4*)(src + (size_t)k * N + nf);
        sT[nf + 0][k] = v.x; sT[nf + 1][k] = v.y;
        sT[nf + 2][k] = v.z; sT[nf + 3][k] = v.w;
    }
    __syncthreads();
    for (int i = tid; i < 128 * 16; i += 256) {
        int n = i >> 4, k4 = (i & 15) * 4;
        uint32_t h0, l0, h1, l1;
        split2(sT[n][k4],     sT[n][k4 + 1], h0, l0);
        split2(sT[n][k4 + 2], sT[n][k4 + 3], h1, l1);
        size_t off = (size_t)(nt * 128 + n) * K + kc * 64 + k4;
        *(uint2*)(hiP + off) = make_uint2(h0, h1);
        *(uint2*)(loP + off) = make_uint2(l0, l1);
    }
}

// ---------------- generic grouped GEMM, bf16x3 via mma.sync ----------------
// jobs: 0 routed G, 1 routed U, 2 routed down, 3 shared G, 4 shared U, 5 shared down
__global__ void __launch_bounds__(256)
mma_gemm(const float* __restrict__ X, int job, int rowsShared)
{
    extern __shared__ char sm[];
    __shared__ int s_tok[128];

    const __nv_bfloat16* Bb; const float* Abase; float* C;
    int K, Nw;
    bool routed = (job <= 2);
    if (job == 0)      { Bb = g_pwg; Abase = X;       C = g_g;     K = H;  Nw = ID; }
    else if (job == 1) { Bb = g_pwu; Abase = X;       C = g_u;     K = H;  Nw = ID; }
    else if (job == 2) { Bb = g_pwd; Abase = g_act;   C = g_outs;  K = ID; Nw = H;  }
    else if (job == 3) { Bb = g_psg; Abase = X;       C = g_shg;   K = H;  Nw = ID; }
    else if (job == 4) { Bb = g_psu; Abase = X;       C = g_shu;   K = H;  Nw = ID; }
    else               { Bb = g_psd; Abase = g_shact; C = g_shout; K = ID; Nw = H;  }

    int e = blockIdx.z;
    int r0, cnt;
    if (routed) { r0 = g_offsets[e]; cnt = g_offsets[e + 1] - r0; }
    else        { r0 = 0; cnt = rowsShared; }
    int mbase = blockIdx.y * 128;
    if (mbase >= cnt) return;
    int nbase = blockIdx.x * 128;

    size_t NK = (size_t)Nw * K;
    const char* BhiG = (const char*)(Bb + (size_t)e * 2 * NK);

    int tid = threadIdx.x;
    int wid = tid >> 5, lane = tid & 31;
    int warpM = wid & 1, warpN = wid >> 1;

    // per-row source index: -1 => zero rows
    if (tid < 128) {
        int rr = mbase + tid;
        int src = -1;
        if (rr < cnt) {
            if (job == 0 || job == 1)      src = g_rowmap[r0 + rr] >> 2; // token id
            else if (job == 2)             src = r0 + rr;                // g_act sorted row
            else                           src = rr;                     // direct
        }
        s_tok[tid] = src;
    }
    __syncthreads();

    uint32_t smbase = smem_u32(sm);
    int ar = tid >> 1, ah2 = tid & 1;           // A fill: row, k-half
    int agr = s_tok[ar];
    const float* aptr = Abase + (size_t)(agr < 0 ? 0 : agr) * K + ah2 * 32;

    float4 areg[8];
    const float4 f4z = make_float4(0.f, 0.f, 0.f, 0.f);

    auto ldA = [&](int c) {
        const float4* p = (const float4*)(aptr + c * KCH);
        #pragma unroll
        for (int j = 0; j < 8; j++) areg[j] = (agr >= 0) ? p[j] : f4z;
    };
    auto stsA = [&](int s) {
        char* Ah = sm + s * STAGE + ar * 144 + ah2 * 64;
        #pragma unroll
        for (int j = 0; j < 8; j++) {
            uint32_t h0, l0, h1, l1;
            split2(areg[j].x, areg[j].y, h0, l0);
            split2(areg[j].z, areg[j].w, h1, l1);
            *(uint2*)(Ah + j * 8)         = make_uint2(h0, h1);
            *(uint2*)(Ah + PLANE + j * 8) = make_uint2(l0, l1);
        }
    };
    auto cpB = [&](int c, int s) {
        uint32_t dstB = smbase + s * STAGE + 2 * PLANE;
        #pragma unroll
        for (int j = 0; j < 8; j++) {
            int idx = j * 256 + tid;            // 2048 x 16B
            int plane = idx >> 10;
            int rem = idx & 1023;
            int rr = rem >> 3, cc = (rem & 7) * 16;
            const char* src = BhiG + ((size_t)plane * NK + (size_t)(nbase + rr) * K
                                      + c * KCH) * 2 + cc;
            uint32_t dst = dstB + plane * PLANE + rr * 144 + cc;
            CP16(dst, src);
        }
    };

    float acc[4][4][4];
    #pragma unroll
    for (int a = 0; a < 4; a++)
        #pragma unroll
        for (int b = 0; b < 4; b++)
            #pragma unroll
            for (int cc2 = 0; cc2 < 4; cc2++) acc[a][b][cc2] = 0.f;

    // ldmatrix per-lane address components
    int arow = (lane & 7) + ((lane >> 3) & 1) * 8;
    int aselB = (lane >> 4) * 16;               // k-half byte offset
    int brow = (lane & 7) + (lane >> 4) * 8;
    int bselB = ((lane >> 3) & 1) * 16;

    auto compute = [&](int s) {
        uint32_t base = smbase + s * STAGE;
        uint32_t AhiS = base, AloS = base + PLANE;
        uint32_t BhiS = base + 2 * PLANE, BloS = base + 3 * PLANE;
        #pragma unroll
        for (int k16 = 0; k16 < 4; k16++) {
            uint32_t ahf[4][4], alf[4][4], bhf[4][2], blf[4][2];
            #pragma unroll
            for (int mi = 0; mi < 4; mi++) {
                uint32_t ra = (uint32_t)((warpM * 64 + mi * 16 + arow) * 144
                                         + k16 * 32 + aselB);
                LDMX4(ahf[mi][0], ahf[mi][1], ahf[mi][2], ahf[mi][3], AhiS + ra);
                LDMX4(alf[mi][0], alf[mi][1], alf[mi][2], alf[mi][3], AloS + ra);
            }
            #pragma unroll
            for (int gi = 0; gi < 2; gi++) {
                uint32_t rb = (uint32_t)((warpN * 32 + gi * 16 + brow) * 144
                                         + k16 * 32 + bselB);
                uint32_t x0, x1, x2, x3;
                LDMX4(x0, x1, x2, x3, BhiS + rb);
                bhf[gi * 2][0] = x0; bhf[gi * 2][1] = x1;
                bhf[gi * 2 + 1][0] = x2; bhf[gi * 2 + 1][1] = x3;
                LDMX4(x0, x1, x2, x3, BloS + rb);
                blf[gi * 2][0] = x0; blf[gi * 2][1] = x1;
                blf[gi * 2 + 1][0] = x2; blf[gi * 2 + 1][1] = x3;
            }
            #pragma unroll
            for (int mi = 0; mi < 4; mi++)
                #pragma unroll
                for (int ni = 0; ni < 4; ni++) {
                    MMA16816(acc[mi][ni], ahf[mi], bhf[ni][0], bhf[ni][1]);
                    MMA16816(acc[mi][ni], ahf[mi], blf[ni][0], blf[ni][1]);
                    MMA16816(acc[mi][ni], alf[mi], bhf[ni][0], bhf[ni][1]);
                }
        }
    };

    int nc = K / KCH;
    ldA(0); stsA(0); cpB(0, 0);
    asm volatile("cp.async.commit_group;");
    asm volatile("cp.async.wait_group 0;" ::: "memory");
    __syncthreads();

    for (int c = 0; c < nc; c++) {
        int s = c & 1;
        if (c + 1 < nc) { ldA(c + 1); cpB(c + 1, s ^ 1); }
        asm volatile("cp.async.commit_group;");
        compute(s);
        if (c + 1 < nc) stsA(s ^ 1);
        asm volatile("cp.async.wait_group 0;" ::: "memory");
        __syncthreads();
    }

    // epilogue
    int g = lane >> 2, tg = lane & 3;
    #pragma unroll
    for (int mi = 0; mi < 4; mi++) {
        int row = mbase + warpM * 64 + mi * 16 + g;
        #pragma unroll
        for (int ni = 0; ni < 4; ni++) {
            int col = nbase + warpN * 32 + ni * 8 + tg * 2;
            if (row < cnt)
                *(float2*)(C + (size_t)(r0 + row) * Nw + col)
                    = make_float2(acc[mi][ni][0], acc[mi][ni][1]);
            if (row + 8 < cnt)
                *(float2*)(C + (size_t)(r0 + row + 8) * Nw + col)
                    = make_float2(acc[mi][ni][2], acc[mi][ni][3]);
        }
    }
}

// ---------------- silu(g)*u -------------------------------------------------
__global__ void __launch_bounds__(256)
silu_mul(int shared_mode, long long total4)
{
    long long i = (long long)blockIdx.x * 256 + threadIdx.x;
    if (i >= total4) return;
    const float4* G = (const float4*)(shared_mode ? g_shg : g_g);
    const float4* U = (const float4*)(shared_mode ? g_shu : g_u);
    float4* A = (float4*)(shared_mode ? g_shact : g_act);
    float4 gv = G[i], uv = U[i], o;
    o.x = silu(gv.x) * uv.x; o.y = silu(gv.y) * uv.y;
    o.z = silu(gv.z) * uv.z; o.w = silu(gv.w) * uv.w;
    A[i] = o;
}

// ---------------- combine ---------------------------------------------------
__global__ void __launch_bounds__(256)
combine_kernel(float* __restrict__ Y)
{
    int t = blockIdx.x;
    __shared__ float w[TK];
    __shared__ int   p[TK];
    if (threadIdx.x < TK) {
        w[threadIdx.x] = g_tw[t * TK + threadIdx.x];
        p[threadIdx.x] = g_pos[t * TK + threadIdx.x];
    }
    __syncthreads();
    int c = threadIdx.x * 4;
    float4 acc = *(const float4*)(g_shout + (size_t)t * H + c);
    #pragma unroll
    for (int k = 0; k < TK; k++) {
        float4 v = *(const float4*)(g_outs + (size_t)p[k] * H + c);
        acc.x += w[k] * v.x; acc.y += w[k] * v.y;
        acc.z += w[k] * v.z; acc.w += w[k] * v.w;
    }
    *(float4*)(Y + (size_t)t * H + c) = acc;
}

__global__ void fill_zero(float* p, long long n) {
    long long i = (long long)blockIdx.x * 256 + threadIdx.x;
    if (i < n) p[i] = 0.f;
}

// ---------------- launch -----------------------------------------------------
extern "C" void kernel_launch(void* const* d_in, const int* in_sizes, int n_in,
                              void* d_out, int out_size)
{
    const float* x   = (const float*)d_in[0];
    const float* gw  = (const float*)d_in[1];
    const float* eb  = (const float*)d_in[2];
    const float* wg  = (const float*)d_in[3];
    const float* wu  = (const float*)d_in[4];
    const float* wd  = (const float*)d_in[5];
    const float* wsg = (const float*)d_in[6];
    const float* wsu = (const float*)d_in[7];
    const float* wsd = (const float*)d_in[8];
    float* out = (float*)d_out;

    int T = in_sizes[0] / H;
    int N = T * TK;
    int MT = (T + 127) / 128;

    long long oL = (long long)T * H;
    long long oK = oL + (long long)T * NE;
    long long oEnd = oK + (long long)T * TK;

    float* outLogits = ((long long)out_size >= oK)   ? (out + oL) : nullptr;
    float* outTopkF  = ((long long)out_size >= oEnd) ? (out + oK) : nullptr;
    long long written = ((long long)out_size >= oEnd) ? oEnd
                       : ((long long)out_size >= oK) ? oK
                       : oL;

    cudaFuncSetAttribute(mma_gemm, cudaFuncAttributeMaxDynamicSharedMemorySize, SMEM_DYN);

    init_kernel<<<1, 32>>>();

    prep_kernel<<<dim3(H / 64,  ID / 128, NE), 256>>>(wg,  H, ID, 0);
    prep_kernel<<<dim3(H / 64,  ID / 128, NE), 256>>>(wu,  H, ID, 1);
    prep_kernel<<<dim3(ID / 64, H / 128,  NE), 256>>>(wd,  ID, H, 2);
    prep_kernel<<<dim3(H / 64,  ID / 128, 1),  256>>>(wsg, H, ID, 3);
    prep_kernel<<<dim3(H / 64,  ID / 128, 1),  256>>>(wsu, H, ID, 4);
    prep_kernel<<<dim3(ID / 64, H / 128,  1),  256>>>(wsd, ID, H, 5);

    gate_kernel<<<T, 128>>>(x, gw, eb, outLogits, outTopkF);
    scan_kernel<<<1, 1>>>();
    scatter_kernel<<<(N + 255) / 256, 256>>>(N);

    // routed experts
    mma_gemm<<<dim3(ID / 128, MT, NE), 256, SMEM_DYN>>>(x, 0, 0);
    mma_gemm<<<dim3(ID / 128, MT, NE), 256, SMEM_DYN>>>(x, 1, 0);
    silu_mul<<<(unsigned)(((long long)N * ID / 4 + 255) / 256), 256>>>(0, (long long)N * ID / 4);
    mma_gemm<<<dim3(H / 128, MT, NE), 256, SMEM_DYN>>>(x, 2, 0);
    // shared expert
    mma_gemm<<<dim3(ID / 128, MT, 1), 256, SMEM_DYN>>>(x, 3, T);
    mma_gemm<<<dim3(ID / 128, MT, 1), 256, SMEM_DYN>>>(x, 4, T);
    silu_mul<<<(unsigned)(((long long)T * ID / 4 + 255) / 256), 256>>>(1, (long long)T * ID / 4);
    mma_gemm<<<dim3(H / 128, MT, 1), 256, SMEM_DYN>>>(x, 5, T);

    combine_kernel<<<T, 256>>>(out);

    if ((long long)out_size > written) {
        long long rest = (long long)out_size - written;
        fill_zero<<<(unsigned)((rest + 255) / 256), 256>>>(out + written, rest);
    }
}

// round 5
// speedup vs baseline: 2.0681x; 1.2552x over previous
#include <cuda_runtime.h>
#include <cuda_bf16.h>
#include <math.h>
#include <stdint.h>

#define H   1024
#define ID  512
#define NE  32
#define TK  4
#define MAXT 4096
#define MAXN (MAXT*TK)
#define RSCALE 2.5f

#define KCH   64
#define ROWB  144                  // bytes per smem row (64 bf16 + pad) conflict-free
#define PLANE (128*ROWB)           // 18432 B
#define STAGE_GU (6*PLANE)         // Ah,Al,Bgh,Bgl,Buh,Bul
#define STAGE_DN (4*PLANE)         // Ah,Al,Bh,Bl
#define SMEM_GU (2*STAGE_GU)       // 221184
#define SMEM_DN (2*STAGE_DN)       // 147456

// ---------------- scratch (device globals; referenced ONLY in device code) --
__device__ float g_outs[(size_t)MAXN * H];
__device__ float g_shout[(size_t)MAXT * H];
__device__ float g_tw[MAXT * TK];
__device__ int   g_topk[MAXT * TK];
__device__ int   g_counts[NE];
__device__ int   g_offsets[NE + 1];
__device__ int   g_cursor[NE];
__device__ int   g_rowmap[MAXN];
__device__ int   g_pos[MAXN];

// bf16 hi/lo planes
__device__ __align__(16) __nv_bfloat16 g_xh[(size_t)MAXT * H];
__device__ __align__(16) __nv_bfloat16 g_xl[(size_t)MAXT * H];
__device__ __align__(16) __nv_bfloat16 g_acth[(size_t)(MAXN + 128) * ID];
__device__ __align__(16) __nv_bfloat16 g_actl[(size_t)(MAXN + 128) * ID];
__device__ __align__(16) __nv_bfloat16 g_shacth[(size_t)MAXT * ID];
__device__ __align__(16) __nv_bfloat16 g_shactl[(size_t)MAXT * ID];

// prepped weights: per expert: hi plane [N][K] bf16, then lo plane [N][K]
__device__ __align__(16) __nv_bfloat16 g_pwg[(size_t)NE*2*ID*H];
__device__ __align__(16) __nv_bfloat16 g_pwu[(size_t)NE*2*ID*H];
__device__ __align__(16) __nv_bfloat16 g_pwd[(size_t)NE*2*H*ID];
__device__ __align__(16) __nv_bfloat16 g_psg[(size_t)2*ID*H];
__device__ __align__(16) __nv_bfloat16 g_psu[(size_t)2*ID*H];
__device__ __align__(16) __nv_bfloat16 g_psd[(size_t)2*H*ID];

// ---------------- helpers ----------------------------------------------
__device__ __forceinline__ uint32_t smem_u32(const void* p) {
    return (uint32_t)__cvta_generic_to_shared(p);
}
__device__ __forceinline__ void split2(float v0, float v1, uint32_t& hi, uint32_t& lo) {
    __nv_bfloat16 h0 = __float2bfloat16_rn(v0), h1 = __float2bfloat16_rn(v1);
    float r0 = v0 - __bfloat162float(h0), r1 = v1 - __bfloat162float(h1);
    __nv_bfloat16 l0 = __float2bfloat16_rn(r0), l1 = __float2bfloat16_rn(r1);
    hi = (uint32_t)(*(uint16_t*)&h0) | ((uint32_t)(*(uint16_t*)&h1) << 16);
    lo = (uint32_t)(*(uint16_t*)&l0) | ((uint32_t)(*(uint16_t*)&l1) << 16);
}
__device__ __forceinline__ float silu_fast(float g) { return g / (1.f + __expf(-g)); }

#define LDMX4(r0_,r1_,r2_,r3_,addr) \
    asm volatile("ldmatrix.sync.aligned.m8n8.x4.shared.b16 {%0,%1,%2,%3}, [%4];" \
        : "=r"(r0_), "=r"(r1_), "=r"(r2_), "=r"(r3_) : "r"(addr))

#define MMA16816(c_, a_, b0_, b1_) \
    asm volatile("mma.sync.aligned.m16n8k16.row.col.f32.bf16.bf16.f32 " \
        "{%0,%1,%2,%3}, {%4,%5,%6,%7}, {%8,%9}, {%0,%1,%2,%3};" \
        : "+f"((c_)[0]), "+f"((c_)[1]), "+f"((c_)[2]), "+f"((c_)[3]) \
        : "r"((a_)[0]), "r"((a_)[1]), "r"((a_)[2]), "r"((a_)[3]), \
          "r"(b0_), "r"(b1_))

#define CP16(dst, src) \
    asm volatile("cp.async.cg.shared.global [%0], [%1], 16;" :: "r"(dst), "l"(src))

// ---------------- init / routing -----------------------------------------
__global__ void init_kernel() {
    int i = threadIdx.x;
    if (i < NE) { g_counts[i] = 0; g_cursor[i] = 0; }
}

__global__ void __launch_bounds__(128)
gate_kernel(const float* __restrict__ X, const float* __restrict__ GW,
            const float* __restrict__ EB,
            float* outLogits, float* outTopkF)
{
    __shared__ __align__(16) float xs[H];
    __shared__ float sl[NE];
    __shared__ float ssc[NE];
    __shared__ float ssrt[NE];

    int t = blockIdx.x;
    const float* x = X + (size_t)t * H;
    for (int c = threadIdx.x; c < H; c += 128) xs[c] = x[c];
    __syncthreads();

    int e = threadIdx.x >> 2, q = threadIdx.x & 3;
    const float* w = GW + (size_t)e * H;
    float s = 0.f;
    int c0 = q * 256;
    #pragma unroll 8
    for (int c = c0; c < c0 + 256; c += 4) {
        float4 xv = *(const float4*)&xs[c];
        float4 wv = *(const float4*)(w + c);
        s += xv.x * wv.x + xv.y * wv.y + xv.z * wv.z + xv.w * wv.w;
    }
    s += __shfl_down_sync(0xffffffffu, s, 2);
    s += __shfl_down_sync(0xffffffffu, s, 1);
    if (q == 0) {
        sl[e] = s;
        if (outLogits) outLogits[(size_t)t * NE + e] = s;
    }
    __syncthreads();

    if (threadIdx.x < NE) {
        float v = sl[threadIdx.x];
        float sc = 1.f / (1.f + expf(-v));
        ssc[threadIdx.x] = sc;
        ssrt[threadIdx.x] = sc + EB[threadIdx.x];
    }
    __syncthreads();

    if (threadIdx.x == 0) {
        float gs[4];
        #pragma unroll
        for (int g = 0; g < 4; g++) {
            float m1 = -1e30f, m2 = -1e30f;
            #pragma unroll
            for (int j = 0; j < 8; j++) {
                float v = ssrt[g * 8 + j];
                if (v > m1) { m2 = m1; m1 = v; }
                else if (v > m2) { m2 = v; }
            }
            gs[g] = m1 + m2;
        }
        int g1 = 0;
        for (int g = 1; g < 4; g++) if (gs[g] > gs[g1]) g1 = g;
        int g2 = -1;
        for (int g = 0; g < 4; g++) {
            if (g == g1) continue;
            if (g2 < 0 || gs[g] > gs[g2]) g2 = g;
        }
        bool used[NE];
        #pragma unroll
        for (int i = 0; i < NE; i++) used[i] = false;
        int idx[TK]; float wts[TK]; float sum = 0.f;
        #pragma unroll
        for (int k = 0; k < TK; k++) {
            int best = -1; float bv = -1e30f;
            for (int i = 0; i < NE; i++) {
                int grp = i >> 3;
                if (grp != g1 && grp != g2) continue;
                if (used[i]) continue;
                if (ssrt[i] > bv) { bv = ssrt[i]; best = i; }
            }
            used[best] = true;
            idx[k] = best;
            wts[k] = ssc[best];
            sum += wts[k];
        }
        float inv = RSCALE / (sum + 1e-20f);
        #pragma unroll
        for (int k = 0; k < TK; k++) {
            g_topk[t * TK + k] = idx[k];
            g_tw[t * TK + k]   = wts[k] * inv;
            if (outTopkF) outTopkF[t * TK + k] = (float)idx[k];
            atomicAdd(&g_counts[idx[k]], 1);
        }
    }
}

__global__ void scan_kernel() {
    if (threadIdx.x == 0) {
        int o = 0;
        for (int e = 0; e < NE; e++) { g_offsets[e] = o; o += g_counts[e]; }
        g_offsets[NE] = o;
    }
}

__global__ void scatter_kernel(int N) {
    int s = blockIdx.x * 256 + threadIdx.x;
    if (s >= N) return;
    int e = g_topk[s];
    int p = g_offsets[e] + atomicAdd(&g_cursor[e], 1);
    g_rowmap[p] = s;
    g_pos[s] = p;
}

// ---------------- X split: f32 -> bf16 hi/lo planes -------------------------
__global__ void __launch_bounds__(256)
prep_x(const float* __restrict__ X, long long n4)
{
    long long i = (long long)blockIdx.x * 256 + threadIdx.x;
    if (i >= n4) return;
    float4 v = *(const float4*)(X + i * 4);
    uint32_t h0, l0, h1, l1;
    split2(v.x, v.y, h0, l0);
    split2(v.z, v.w, h1, l1);
    *(uint2*)(g_xh + i * 4) = make_uint2(h0, h1);
    *(uint2*)(g_xl + i * 4) = make_uint2(l0, l1);
}

// ---------------- weight prep: W[k][n] f32 -> [n][K] bf16 hi/lo planes ----
__global__ void __launch_bounds__(256)
prep_kernel(const float* __restrict__ W, int K, int N, int which)
{
    __shared__ float sT[128][65];
    int kc = blockIdx.x, nt = blockIdx.y, e = blockIdx.z;
    __nv_bfloat16* pB =
        which == 0 ? g_pwg : which == 1 ? g_pwu : which == 2 ? g_pwd :
        which == 3 ? g_psg : which == 4 ? g_psu : g_psd;
    size_t NK = (size_t)N * K;
    __nv_bfloat16* hiP = pB + (size_t)e * 2 * NK;
    __nv_bfloat16* loP = hiP + NK;
    const float* src = W + ((size_t)e * K + (size_t)kc * 64) * N + (size_t)nt * 128;

    int tid = threadIdx.x;
    for (int i = tid; i < 64 * 32; i += 256) {
        int k = i >> 5, nf = (i & 31) * 4;
        float4 v = *(const float4*)(src + (size_t)k * N + nf);
        sT[nf + 0][k] = v.x; sT[nf + 1][k] = v.y;
        sT[nf + 2][k] = v.z; sT[nf + 3][k] = v.w;
    }
    __syncthreads();
    for (int i = tid; i < 128 * 16; i += 256) {
        int n = i >> 4, k4 = (i & 15) * 4;
        uint32_t h0, l0, h1, l1;
        split2(sT[n][k4],     sT[n][k4 + 1], h0, l0);
        split2(sT[n][k4 + 2], sT[n][k4 + 3], h1, l1);
        size_t off = (size_t)(nt * 128 + n) * K + kc * 64 + k4;
        *(uint2*)(hiP + off) = make_uint2(h0, h1);
        *(uint2*)(loP + off) = make_uint2(l0, l1);
    }
}

// ---------------- fused gate+up GEMM (bf16x3, cp.async only) ---------------
__global__ void __launch_bounds__(256)
mma_gateup(int shared_mode, int rowsShared)
{
    extern __shared__ char sm[];
    __shared__ int s_tok[128];

    int e = blockIdx.z;
    int r0, cnt;
    if (shared_mode) { r0 = 0; cnt = rowsShared; }
    else { r0 = g_offsets[e]; cnt = g_offsets[e + 1] - r0; }
    int mbase = blockIdx.y * 128;
    if (mbase >= cnt) return;
    int nbase = blockIdx.x * 128;

    const size_t NK = (size_t)ID * H;
    const __nv_bfloat16* Bg = (shared_mode ? g_psg : g_pwg) + (size_t)e * 2 * NK;
    const __nv_bfloat16* Bu = (shared_mode ? g_psu : g_pwu) + (size_t)e * 2 * NK;

    int tid = threadIdx.x;
    int wid = tid >> 5, lane = tid & 31;
    int warpM = wid & 1, warpN = wid >> 1;

    if (tid < 128) {
        int rr = mbase + tid;
        int src = -1;
        if (rr < cnt) src = shared_mode ? rr : (g_rowmap[r0 + rr] >> 2);
        s_tok[tid] = src;
    }
    __syncthreads();

    uint32_t smbase = smem_u32(sm);

    auto fill = [&](int c, int s) {
        uint32_t st = smbase + s * STAGE_GU;
        // A: 2 planes x 128 rows x 8 x 16B, gathered by token
        #pragma unroll
        for (int j = 0; j < 8; j++) {
            int idx = j * 256 + tid;
            int plane = idx >> 10;
            int rem = idx & 1023;
            int row = rem >> 3, seg = rem & 7;
            int t = s_tok[row];
            uint32_t dst = st + plane * PLANE + row * ROWB + seg * 16;
            if (t >= 0) {
                const __nv_bfloat16* src =
                    (plane ? g_xl : g_xh) + (size_t)t * H + c * KCH + seg * 8;
                CP16(dst, src);
            } else {
                *(uint4*)(sm + (dst - smbase)) = make_uint4(0, 0, 0, 0);
            }
        }
        // B: 4 planes (bgh,bgl,buh,bul)
        #pragma unroll
        for (int j = 0; j < 16; j++) {
            int idx = j * 256 + tid;
            int plane = idx >> 10;
            int rem = idx & 1023;
            int row = rem >> 3, seg = rem & 7;
            const __nv_bfloat16* base = (plane < 2 ? Bg : Bu) + (size_t)(plane & 1) * NK;
            const __nv_bfloat16* src = base + (size_t)(nbase + row) * H + c * KCH + seg * 8;
            CP16(st + (2 + plane) * PLANE + row * ROWB + seg * 16, src);
        }
    };

    float accG[4][4][4], accU[4][4][4];
    #pragma unroll
    for (int a = 0; a < 4; a++)
        #pragma unroll
        for (int b = 0; b < 4; b++)
            #pragma unroll
            for (int cc = 0; cc < 4; cc++) { accG[a][b][cc] = 0.f; accU[a][b][cc] = 0.f; }

    int arow = (lane & 7) + ((lane >> 3) & 1) * 8;
    int aselB = (lane >> 4) * 16;
    int brow = (lane & 7) + (lane >> 4) * 8;
    int bselB = ((lane >> 3) & 1) * 16;

    auto compute = [&](int s) {
        uint32_t base = smbase + s * STAGE_GU;
        #pragma unroll
        for (int k16 = 0; k16 < 4; k16++) {
            uint32_t a[4][4], bh[4][2], bl[4][2];
            // --- G ---
            #pragma unroll
            for (int gi = 0; gi < 2; gi++) {
                uint32_t rb = (uint32_t)((warpN * 32 + gi * 16 + brow) * ROWB
                                         + k16 * 32 + bselB);
                uint32_t x0, x1, x2, x3;
                LDMX4(x0, x1, x2, x3, base + 2 * PLANE + rb);
                bh[gi*2][0]=x0; bh[gi*2][1]=x1; bh[gi*2+1][0]=x2; bh[gi*2+1][1]=x3;
                LDMX4(x0, x1, x2, x3, base + 3 * PLANE + rb);
                bl[gi*2][0]=x0; bl[gi*2][1]=x1; bl[gi*2+1][0]=x2; bl[gi*2+1][1]=x3;
            }
            #pragma unroll
            for (int mi = 0; mi < 4; mi++) {
                uint32_t ra = (uint32_t)((warpM * 64 + mi * 16 + arow) * ROWB
                                         + k16 * 32 + aselB);
                LDMX4(a[mi][0], a[mi][1], a[mi][2], a[mi][3], base + ra);
            }
            #pragma unroll
            for (int mi = 0; mi < 4; mi++)
                #pragma unroll
                for (int ni = 0; ni < 4; ni++) {
                    MMA16816(accG[mi][ni], a[mi], bh[ni][0], bh[ni][1]);
                    MMA16816(accG[mi][ni], a[mi], bl[ni][0], bl[ni][1]);
                }
            #pragma unroll
            for (int mi = 0; mi < 4; mi++) {
                uint32_t ra = (uint32_t)((warpM * 64 + mi * 16 + arow) * ROWB
                                         + k16 * 32 + aselB);
                LDMX4(a[mi][0], a[mi][1], a[mi][2], a[mi][3], base + PLANE + ra);
            }
            #pragma unroll
            for (int mi = 0; mi < 4; mi++)
                #pragma unroll
                for (int ni = 0; ni < 4; ni++)
                    MMA16816(accG[mi][ni], a[mi], bh[ni][0], bh[ni][1]);
            // --- U ---
            #pragma unroll
            for (int gi = 0; gi < 2; gi++) {
                uint32_t rb = (uint32_t)((warpN * 32 + gi * 16 + brow) * ROWB
                                         + k16 * 32 + bselB);
                uint32_t x0, x1, x2, x3;
                LDMX4(x0, x1, x2, x3, base + 4 * PLANE + rb);
                bh[gi*2][0]=x0; bh[gi*2][1]=x1; bh[gi*2+1][0]=x2; bh[gi*2+1][1]=x3;
                LDMX4(x0, x1, x2, x3, base + 5 * PLANE + rb);
                bl[gi*2][0]=x0; bl[gi*2][1]=x1; bl[gi*2+1][0]=x2; bl[gi*2+1][1]=x3;
            }
            #pragma unroll
            for (int mi = 0; mi < 4; mi++) {
                uint32_t ra = (uint32_t)((warpM * 64 + mi * 16 + arow) * ROWB
                                         + k16 * 32 + aselB);
                LDMX4(a[mi][0], a[mi][1], a[mi][2], a[mi][3], base + ra);
            }
            #pragma unroll
            for (int mi = 0; mi < 4; mi++)
                #pragma unroll
                for (int ni = 0; ni < 4; ni++) {
                    MMA16816(accU[mi][ni], a[mi], bh[ni][0], bh[ni][1]);
                    MMA16816(accU[mi][ni], a[mi], bl[ni][0], bl[ni][1]);
                }
            #pragma unroll
            for (int mi = 0; mi < 4; mi++) {
                uint32_t ra = (uint32_t)((warpM * 64 + mi * 16 + arow) * ROWB
                                         + k16 * 32 + aselB);
                LDMX4(a[mi][0], a[mi][1], a[mi][2], a[mi][3], base + PLANE + ra);
            }
            #pragma unroll
            for (int mi = 0; mi < 4; mi++)
                #pragma unroll
                for (int ni = 0; ni < 4; ni++)
                    MMA16816(accU[mi][ni], a[mi], bh[ni][0], bh[ni][1]);
        }
    };

    const int nc = H / KCH;   // 16
    fill(0, 0);
    asm volatile("cp.async.commit_group;");

    for (int c = 0; c < nc; c++) {
        int s = c & 1;
        if (c + 1 < nc) {
            fill(c + 1, s ^ 1);
            asm volatile("cp.async.commit_group;");
            asm volatile("cp.async.wait_group 1;" ::: "memory");
        } else {
            asm volatile("cp.async.wait_group 0;" ::: "memory");
        }
        __syncthreads();
        compute(s);
        __syncthreads();
    }

    // epilogue: act = silu(G)*U -> bf16 hi/lo planes
    __nv_bfloat16* Ah = shared_mode ? g_shacth : g_acth;
    __nv_bfloat16* Al = shared_mode ? g_shactl : g_actl;
    int g = lane >> 2, tg = lane & 3;
    #pragma unroll
    for (int mi = 0; mi < 4; mi++) {
        int row = mbase + warpM * 64 + mi * 16 + g;
        #pragma unroll
        for (int ni = 0; ni < 4; ni++) {
            int col = nbase + warpN * 32 + ni * 8 + tg * 2;
            if (row < cnt) {
                float a0 = silu_fast(accG[mi][ni][0]) * accU[mi][ni][0];
                float a1 = silu_fast(accG[mi][ni][1]) * accU[mi][ni][1];
                uint32_t hi, lo;
                split2(a0, a1, hi, lo);
                size_t off = (size_t)(r0 + row) * ID + col;
                *(uint32_t*)(Ah + off) = hi;
                *(uint32_t*)(Al + off) = lo;
            }
            if (row + 8 < cnt) {
                float a0 = silu_fast(accG[mi][ni][2]) * accU[mi][ni][2];
                float a1 = silu_fast(accG[mi][ni][3]) * accU[mi][ni][3];
                uint32_t hi, lo;
                split2(a0, a1, hi, lo);
                size_t off = (size_t)(r0 + row + 8) * ID + col;
                *(uint32_t*)(Ah + off) = hi;
                *(uint32_t*)(Al + off) = lo;
            }
        }
    }
}

// ---------------- down GEMM (bf16x3, cp.async only) -------------------------
__global__ void __launch_bounds__(256)
mma_down(int shared_mode, int rowsShared)
{
    extern __shared__ char sm[];

    int e = blockIdx.z;
    int r0, cnt;
    if (shared_mode) { r0 = 0; cnt = rowsShared; }
    else { r0 = g_offsets[e]; cnt = g_offsets[e + 1] - r0; }
    int mbase = blockIdx.y * 128;
    if (mbase >= cnt) return;
    int nbase = blockIdx.x * 128;

    const size_t NK = (size_t)H * ID;
    const __nv_bfloat16* Bd = (shared_mode ? g_psd : g_pwd) + (size_t)e * 2 * NK;
    const __nv_bfloat16* Ahp = shared_mode ? g_shacth : g_acth;
    const __nv_bfloat16* Alp = shared_mode ? g_shactl : g_actl;
    float* C = shared_mode ? g_shout : g_outs;

    int tid = threadIdx.x;
    int wid = tid >> 5, lane = tid & 31;
    int warpM = wid & 1, warpN = wid >> 1;

    uint32_t smbase = smem_u32(sm);

    auto fill = [&](int c, int s) {
        uint32_t st = smbase + s * STAGE_DN;
        #pragma unroll
        for (int j = 0; j < 16; j++) {
            int idx = j * 256 + tid;          // 4096: Ah, Al, Bh, Bl
            int plane = idx >> 10;
            int rem = idx & 1023;
            int row = rem >> 3, seg = rem & 7;
            const __nv_bfloat16* src;
            if (plane < 2)
                src = (plane ? Alp : Ahp) + (size_t)(r0 + mbase + row) * ID + c * KCH + seg * 8;
            else
                src = Bd + (size_t)(plane & 1) * NK + (size_t)(nbase + row) * ID + c * KCH + seg * 8;
            CP16(st + plane * PLANE + row * ROWB + seg * 16, src);
        }
    };

    float acc[4][4][4];
    #pragma unroll
    for (int a = 0; a < 4; a++)
        #pragma unroll
        for (int b = 0; b < 4; b++)
            #pragma unroll
            for (int cc = 0; cc < 4; cc++) acc[a][b][cc] = 0.f;

    int arow = (lane & 7) + ((lane >> 3) & 1) * 8;
    int aselB = (lane >> 4) * 16;
    int brow = (lane & 7) + (lane >> 4) * 8;
    int bselB = ((lane >> 3) & 1) * 16;

    auto compute = [&](int s) {
        uint32_t base = smbase + s * STAGE_DN;
        #pragma unroll
        for (int k16 = 0; k16 < 4; k16++) {
            uint32_t a[4][4], bh[4][2], bl[4][2];
            #pragma unroll
            for (int gi = 0; gi < 2; gi++) {
                uint32_t rb = (uint32_t)((warpN * 32 + gi * 16 + brow) * ROWB
                                         + k16 * 32 + bselB);
                uint32_t x0, x1, x2, x3;
                LDMX4(x0, x1, x2, x3, base + 2 * PLANE + rb);
                bh[gi*2][0]=x0; bh[gi*2][1]=x1; bh[gi*2+1][0]=x2; bh[gi*2+1][1]=x3;
                LDMX4(x0, x1, x2, x3, base + 3 * PLANE + rb);
                bl[gi*2][0]=x0; bl[gi*2][1]=x1; bl[gi*2+1][0]=x2; bl[gi*2+1][1]=x3;
            }
            #pragma unroll
            for (int mi = 0; mi < 4; mi++) {
                uint32_t ra = (uint32_t)((warpM * 64 + mi * 16 + arow) * ROWB
                                         + k16 * 32 + aselB);
                LDMX4(a[mi][0], a[mi][1], a[mi][2], a[mi][3], base + ra);
            }
            #pragma unroll
            for (int mi = 0; mi < 4; mi++)
                #pragma unroll
                for (int ni = 0; ni < 4; ni++) {
                    MMA16816(acc[mi][ni], a[mi], bh[ni][0], bh[ni][1]);
                    MMA16816(acc[mi][ni], a[mi], bl[ni][0], bl[ni][1]);
                }
            #pragma unroll
            for (int mi = 0; mi < 4; mi++) {
                uint32_t ra = (uint32_t)((warpM * 64 + mi * 16 + arow) * ROWB
                                         + k16 * 32 + aselB);
                LDMX4(a[mi][0], a[mi][1], a[mi][2], a[mi][3], base + PLANE + ra);
            }
            #pragma unroll
            for (int mi = 0; mi < 4; mi++)
                #pragma unroll
                for (int ni = 0; ni < 4; ni++)
                    MMA16816(acc[mi][ni], a[mi], bh[ni][0], bh[ni][1]);
        }
    };

    const int nc = ID / KCH;    // 8
    fill(0, 0);
    asm volatile("cp.async.commit_group;");

    for (int c = 0; c < nc; c++) {
        int s = c & 1;
        if (c + 1 < nc) {
            fill(c + 1, s ^ 1);
            asm volatile("cp.async.commit_group;");
            asm volatile("cp.async.wait_group 1;" ::: "memory");
        } else {
            asm volatile("cp.async.wait_group 0;" ::: "memory");
        }
        __syncthreads();
        compute(s);
        __syncthreads();
    }

    int g = lane >> 2, tg = lane & 3;
    #pragma unroll
    for (int mi = 0; mi < 4; mi++) {
        int row = mbase + warpM * 64 + mi * 16 + g;
        #pragma unroll
        for (int ni = 0; ni < 4; ni++) {
            int col = nbase + warpN * 32 + ni * 8 + tg * 2;
            if (row < cnt)
                *(float2*)(C + (size_t)(r0 + row) * H + col)
                    = make_float2(acc[mi][ni][0], acc[mi][ni][1]);
            if (row + 8 < cnt)
                *(float2*)(C + (size_t)(r0 + row + 8) * H + col)
                    = make_float2(acc[mi][ni][2], acc[mi][ni][3]);
        }
    }
}

// ---------------- combine ---------------------------------------------------
__global__ void __launch_bounds__(256)
combine_kernel(float* __restrict__ Y)
{
    int t = blockIdx.x;
    __shared__ float w[TK];
    __shared__ int   p[TK];
    if (threadIdx.x < TK) {
        w[threadIdx.x] = g_tw[t * TK + threadIdx.x];
        p[threadIdx.x] = g_pos[t * TK + threadIdx.x];
    }
    __syncthreads();
    int c = threadIdx.x * 4;
    float4 acc = *(const float4*)(g_shout + (size_t)t * H + c);
    #pragma unroll
    for (int k = 0; k < TK; k++) {
        float4 v = *(const float4*)(g_outs + (size_t)p[k] * H + c);
        acc.x += w[k] * v.x; acc.y += w[k] * v.y;
        acc.z += w[k] * v.z; acc.w += w[k] * v.w;
    }
    *(float4*)(Y + (size_t)t * H + c) = acc;
}

__global__ void fill_zero(float* p, long long n) {
    long long i = (long long)blockIdx.x * 256 + threadIdx.x;
    if (i < n) p[i] = 0.f;
}

// ---------------- launch -----------------------------------------------------
extern "C" void kernel_launch(void* const* d_in, const int* in_sizes, int n_in,
                              void* d_out, int out_size)
{
    const float* x   = (const float*)d_in[0];
    const float* gw  = (const float*)d_in[1];
    const float* eb  = (const float*)d_in[2];
    const float* wg  = (const float*)d_in[3];
    const float* wu  = (const float*)d_in[4];
    const float* wd  = (const float*)d_in[5];
    const float* wsg = (const float*)d_in[6];
    const float* wsu = (const float*)d_in[7];
    const float* wsd = (const float*)d_in[8];
    float* out = (float*)d_out;

    int T = in_sizes[0] / H;
    int N = T * TK;
    int MT = (T + 127) / 128;

    long long oL = (long long)T * H;
    long long oK = oL + (long long)T * NE;
    long long oEnd = oK + (long long)T * TK;

    float* outLogits = ((long long)out_size >= oK)   ? (out + oL) : nullptr;
    float* outTopkF  = ((long long)out_size >= oEnd) ? (out + oK) : nullptr;
    long long written = ((long long)out_size >= oEnd) ? oEnd
                       : ((long long)out_size >= oK) ? oK
                       : oL;

    cudaFuncSetAttribute(mma_gateup, cudaFuncAttributeMaxDynamicSharedMemorySize, SMEM_GU);
    cudaFuncSetAttribute(mma_down,   cudaFuncAttributeMaxDynamicSharedMemorySize, SMEM_DN);

    // shared-expert chain first (also puts a GEMM at ncu's -s 5 slot)
    prep_kernel<<<dim3(H / 64,  ID / 128, 1),  256>>>(wsg, H, ID, 3);
    prep_kernel<<<dim3(H / 64,  ID / 128, 1),  256>>>(wsu, H, ID, 4);
    prep_kernel<<<dim3(ID / 64, H / 128,  1),  256>>>(wsd, ID, H, 5);
    prep_x<<<(unsigned)(((long long)T * H / 4 + 255) / 256), 256>>>(x, (long long)T * H / 4);
    mma_gateup<<<dim3(ID / 128, MT, 1), 256, SMEM_GU>>>(1, T);
    mma_down  <<<dim3(H / 128,  MT, 1), 256, SMEM_DN>>>(1, T);

    // routing
    init_kernel<<<1, 32>>>();
    gate_kernel<<<T, 128>>>(x, gw, eb, outLogits, outTopkF);
    scan_kernel<<<1, 1>>>();
    scatter_kernel<<<(N + 255) / 256, 256>>>(N);

    // routed expert weights + GEMMs
    prep_kernel<<<dim3(H / 64,  ID / 128, NE), 256>>>(wg,  H, ID, 0);
    prep_kernel<<<dim3(H / 64,  ID / 128, NE), 256>>>(wu,  H, ID, 1);
    prep_kernel<<<dim3(ID / 64, H / 128,  NE), 256>>>(wd,  ID, H, 2);
    mma_gateup<<<dim3(ID / 128, MT, NE), 256, SMEM_GU>>>(0, 0);
    mma_down  <<<dim3(H / 128,  MT, NE), 256, SMEM_DN>>>(0, 0);

    combine_kernel<<<T, 256>>>(out);

    if ((long long)out_size > written) {
        long long rest = (long long)out_size - written;
        fill_zero<<<(unsigned)((rest + 255) / 256), 256>>>(out + written, rest);
    }
}

// round 6
// speedup vs baseline: 2.6674x; 1.2898x over previous
#include <cuda_runtime.h>
#include <cuda_fp16.h>
#include <math.h>
#include <stdint.h>

#define H   1024
#define ID  512
#define NE  32
#define TK  4
#define MAXT 4096
#define MAXN (MAXT*TK)
#define RSCALE 2.5f

#define KCH   64
#define ROWB  144                  // bytes per smem row (64 fp16 + pad), conflict-free
#define PLANE (128*ROWB)           // 18432 B
#define STAGE_GU (4*PLANE)         // Ahi, Alo, Bg, Bu
#define STAGE_DN (3*PLANE)         // Ahi, Alo, B
#define SMEM_GU (2*STAGE_GU)       // 147456
#define SMEM_DN (2*STAGE_DN)       // 110592

// ---------------- scratch (device globals; referenced ONLY in device code) --
__device__ float g_outs[(size_t)MAXN * H];
__device__ float g_shout[(size_t)MAXT * H];
__device__ float g_tw[MAXT * TK];
__device__ int   g_topk[MAXT * TK];
__device__ int   g_counts[NE];
__device__ int   g_offsets[NE + 1];
__device__ int   g_cursor[NE];
__device__ int   g_rowmap[MAXN];
__device__ int   g_pos[MAXN];

// fp16 planes
__device__ __align__(16) __half g_xh[(size_t)MAXT * H];
__device__ __align__(16) __half g_xl[(size_t)MAXT * H];
__device__ __align__(16) __half g_acth[(size_t)(MAXN + 128) * ID];
__device__ __align__(16) __half g_actl[(size_t)(MAXN + 128) * ID];
__device__ __align__(16) __half g_shacth[(size_t)MAXT * ID];
__device__ __align__(16) __half g_shactl[(size_t)MAXT * ID];

// prepped weights: fp16 single plane, [n][K] per expert
__device__ __align__(16) __half g_pwg[(size_t)NE*ID*H];
__device__ __align__(16) __half g_pwu[(size_t)NE*ID*H];
__device__ __align__(16) __half g_pwd[(size_t)NE*H*ID];
__device__ __align__(16) __half g_psg[(size_t)ID*H];
__device__ __align__(16) __half g_psu[(size_t)ID*H];
__device__ __align__(16) __half g_psd[(size_t)H*ID];

// ---------------- helpers ----------------------------------------------
__device__ __forceinline__ uint32_t smem_u32(const void* p) {
    return (uint32_t)__cvta_generic_to_shared(p);
}
__device__ __forceinline__ uint32_t packh(__half a, __half b) {
    return (uint32_t)(*(uint16_t*)&a) | ((uint32_t)(*(uint16_t*)&b) << 16);
}
__device__ __forceinline__ void split2h(float v0, float v1, uint32_t& hi, uint32_t& lo) {
    __half h0 = __float2half_rn(v0), h1 = __float2half_rn(v1);
    float r0 = v0 - __half2float(h0), r1 = v1 - __half2float(h1);
    hi = packh(h0, h1);
    lo = packh(__float2half_rn(r0), __float2half_rn(r1));
}
__device__ __forceinline__ float silu_fast(float g) { return g / (1.f + __expf(-g)); }

#define LDMX4(r0_,r1_,r2_,r3_,addr) \
    asm volatile("ldmatrix.sync.aligned.m8n8.x4.shared.b16 {%0,%1,%2,%3}, [%4];" \
        : "=r"(r0_), "=r"(r1_), "=r"(r2_), "=r"(r3_) : "r"(addr))

#define MMAH(c_, a_, b0_, b1_) \
    asm volatile("mma.sync.aligned.m16n8k16.row.col.f32.f16.f16.f32 " \
        "{%0,%1,%2,%3}, {%4,%5,%6,%7}, {%8,%9}, {%0,%1,%2,%3};" \
        : "+f"((c_)[0]), "+f"((c_)[1]), "+f"((c_)[2]), "+f"((c_)[3]) \
        : "r"((a_)[0]), "r"((a_)[1]), "r"((a_)[2]), "r"((a_)[3]), \
          "r"(b0_), "r"(b1_))

#define CP16(dst, src) \
    asm volatile("cp.async.cg.shared.global [%0], [%1], 16;" :: "r"(dst), "l"(src))

// ---------------- init / routing -----------------------------------------
__global__ void init_kernel() {
    int i = threadIdx.x;
    if (i < NE) { g_counts[i] = 0; g_cursor[i] = 0; }
}

__global__ void __launch_bounds__(128)
gate_kernel(const float* __restrict__ X, const float* __restrict__ GW,
            const float* __restrict__ EB,
            float* outLogits, float* outTopkF)
{
    __shared__ __align__(16) float xs[H];
    __shared__ float sl[NE];
    __shared__ float ssc[NE];
    __shared__ float ssrt[NE];

    int t = blockIdx.x;
    const float* x = X + (size_t)t * H;
    for (int c = threadIdx.x; c < H; c += 128) xs[c] = x[c];
    __syncthreads();

    int e = threadIdx.x >> 2, q = threadIdx.x & 3;
    const float* w = GW + (size_t)e * H;
    float s = 0.f;
    int c0 = q * 256;
    #pragma unroll 8
    for (int c = c0; c < c0 + 256; c += 4) {
        float4 xv = *(const float4*)&xs[c];
        float4 wv = *(const float4*)(w + c);
        s += xv.x * wv.x + xv.y * wv.y + xv.z * wv.z + xv.w * wv.w;
    }
    s += __shfl_down_sync(0xffffffffu, s, 2);
    s += __shfl_down_sync(0xffffffffu, s, 1);
    if (q == 0) {
        sl[e] = s;
        if (outLogits) outLogits[(size_t)t * NE + e] = s;
    }
    __syncthreads();

    if (threadIdx.x < NE) {
        float v = sl[threadIdx.x];
        float sc = 1.f / (1.f + expf(-v));
        ssc[threadIdx.x] = sc;
        ssrt[threadIdx.x] = sc + EB[threadIdx.x];
    }
    __syncthreads();

    if (threadIdx.x == 0) {
        float gs[4];
        #pragma unroll
        for (int g = 0; g < 4; g++) {
            float m1 = -1e30f, m2 = -1e30f;
            #pragma unroll
            for (int j = 0; j < 8; j++) {
                float v = ssrt[g * 8 + j];
                if (v > m1) { m2 = m1; m1 = v; }
                else if (v > m2) { m2 = v; }
            }
            gs[g] = m1 + m2;
        }
        int g1 = 0;
        for (int g = 1; g < 4; g++) if (gs[g] > gs[g1]) g1 = g;
        int g2 = -1;
        for (int g = 0; g < 4; g++) {
            if (g == g1) continue;
            if (g2 < 0 || gs[g] > gs[g2]) g2 = g;
        }
        bool used[NE];
        #pragma unroll
        for (int i = 0; i < NE; i++) used[i] = false;
        int idx[TK]; float wts[TK]; float sum = 0.f;
        #pragma unroll
        for (int k = 0; k < TK; k++) {
            int best = -1; float bv = -1e30f;
            for (int i = 0; i < NE; i++) {
                int grp = i >> 3;
                if (grp != g1 && grp != g2) continue;
                if (used[i]) continue;
                if (ssrt[i] > bv) { bv = ssrt[i]; best = i; }
            }
            used[best] = true;
            idx[k] = best;
            wts[k] = ssc[best];
            sum += wts[k];
        }
        float inv = RSCALE / (sum + 1e-20f);
        #pragma unroll
        for (int k = 0; k < TK; k++) {
            g_topk[t * TK + k] = idx[k];
            g_tw[t * TK + k]   = wts[k] * inv;
            if (outTopkF) outTopkF[t * TK + k] = (float)idx[k];
            atomicAdd(&g_counts[idx[k]], 1);
        }
    }
}

__global__ void scan_kernel() {
    if (threadIdx.x == 0) {
        int o = 0;
        for (int e = 0; e < NE; e++) { g_offsets[e] = o; o += g_counts[e]; }
        g_offsets[NE] = o;
    }
}

__global__ void scatter_kernel(int N) {
    int s = blockIdx.x * 256 + threadIdx.x;
    if (s >= N) return;
    int e = g_topk[s];
    int p = g_offsets[e] + atomicAdd(&g_cursor[e], 1);
    g_rowmap[p] = s;
    g_pos[s] = p;
}

// ---------------- X split: f32 -> fp16 hi/lo planes -------------------------
__global__ void __launch_bounds__(256)
prep_x(const float* __restrict__ X, long long n4)
{
    long long i = (long long)blockIdx.x * 256 + threadIdx.x;
    if (i >= n4) return;
    float4 v = *(const float4*)(X + i * 4);
    uint32_t h0, l0, h1, l1;
    split2h(v.x, v.y, h0, l0);
    split2h(v.z, v.w, h1, l1);
    *(uint2*)(g_xh + i * 4) = make_uint2(h0, h1);
    *(uint2*)(g_xl + i * 4) = make_uint2(l0, l1);
}

// ---------------- weight prep: W[k][n] f32 -> [n][K] fp16 plane -----------
__global__ void __launch_bounds__(256)
prep_kernel(const float* __restrict__ W, int K, int N, int which)
{
    __shared__ float sT[128][65];
    int kc = blockIdx.x, nt = blockIdx.y, e = blockIdx.z;
    __half* pB =
        which == 0 ? g_pwg : which == 1 ? g_pwu : which == 2 ? g_pwd :
        which == 3 ? g_psg : which == 4 ? g_psu : g_psd;
    size_t NK = (size_t)N * K;
    __half* dstP = pB + (size_t)e * NK;
    const float* src = W + ((size_t)e * K + (size_t)kc * 64) * N + (size_t)nt * 128;

    int tid = threadIdx.x;
    for (int i = tid; i < 64 * 32; i += 256) {
        int k = i >> 5, nf = (i & 31) * 4;
        float4 v = *(const float4*)(src + (size_t)k * N + nf);
        sT[nf + 0][k] = v.x; sT[nf + 1][k] = v.y;
        sT[nf + 2][k] = v.z; sT[nf + 3][k] = v.w;
    }
    __syncthreads();
    for (int i = tid; i < 128 * 16; i += 256) {
        int n = i >> 4, k4 = (i & 15) * 4;
        uint32_t a = packh(__float2half_rn(sT[n][k4]),     __float2half_rn(sT[n][k4 + 1]));
        uint32_t b = packh(__float2half_rn(sT[n][k4 + 2]), __float2half_rn(sT[n][k4 + 3]));
        size_t off = (size_t)(nt * 128 + n) * K + kc * 64 + k4;
        *(uint2*)(dstP + off) = make_uint2(a, b);
    }
}

// ---------------- fused gate+up GEMM (fp16 x2 emulation) -------------------
__global__ void __launch_bounds__(256)
mma_gateup(int shared_mode, int rowsShared)
{
    extern __shared__ char sm[];
    __shared__ int s_tok[128];

    int e = blockIdx.z;
    int r0, cnt;
    if (shared_mode) { r0 = 0; cnt = rowsShared; }
    else { r0 = g_offsets[e]; cnt = g_offsets[e + 1] - r0; }
    int mbase = blockIdx.y * 128;
    if (mbase >= cnt) return;
    int nbase = blockIdx.x * 128;

    const size_t NK = (size_t)ID * H;
    const __half* Bg = (shared_mode ? g_psg : g_pwg) + (size_t)e * NK;
    const __half* Bu = (shared_mode ? g_psu : g_pwu) + (size_t)e * NK;

    int tid = threadIdx.x;
    int wid = tid >> 5, lane = tid & 31;
    int warpM = wid & 1, warpN = wid >> 1;

    if (tid < 128) {
        int rr = mbase + tid;
        int src = -1;
        if (rr < cnt) src = shared_mode ? rr : (g_rowmap[r0 + rr] >> 2);
        s_tok[tid] = src;
    }
    __syncthreads();

    uint32_t smbase = smem_u32(sm);

    auto fill = [&](int c, int s) {
        uint32_t st = smbase + s * STAGE_GU;
        // A: 2 planes (hi, lo), gathered by token
        #pragma unroll
        for (int j = 0; j < 8; j++) {
            int idx = j * 256 + tid;
            int plane = idx >> 10;
            int rem = idx & 1023;
            int row = rem >> 3, seg = rem & 7;
            int t = s_tok[row];
            uint32_t dst = st + plane * PLANE + row * ROWB + seg * 16;
            if (t >= 0) {
                const __half* src = (plane ? g_xl : g_xh) + (size_t)t * H + c * KCH + seg * 8;
                CP16(dst, src);
            } else {
                *(uint4*)(sm + (dst - smbase)) = make_uint4(0, 0, 0, 0);
            }
        }
        // B: 2 planes (Bg, Bu)
        #pragma unroll
        for (int j = 0; j < 8; j++) {
            int idx = j * 256 + tid;
            int plane = idx >> 10;
            int rem = idx & 1023;
            int row = rem >> 3, seg = rem & 7;
            const __half* src = (plane ? Bu : Bg) + (size_t)(nbase + row) * H + c * KCH + seg * 8;
            CP16(st + (2 + plane) * PLANE + row * ROWB + seg * 16, src);
        }
    };

    float accG[4][4][4], accU[4][4][4];
    #pragma unroll
    for (int a = 0; a < 4; a++)
        #pragma unroll
        for (int b = 0; b < 4; b++)
            #pragma unroll
            for (int cc = 0; cc < 4; cc++) { accG[a][b][cc] = 0.f; accU[a][b][cc] = 0.f; }

    int arow = (lane & 7) + ((lane >> 3) & 1) * 8;
    int aselB = (lane >> 4) * 16;
    int brow = (lane & 7) + (lane >> 4) * 8;
    int bselB = ((lane >> 3) & 1) * 16;

    auto compute = [&](int s) {
        uint32_t base = smbase + s * STAGE_GU;
        #pragma unroll
        for (int k16 = 0; k16 < 4; k16++) {
            uint32_t ah[4][4], al[4][4], b[4][2];
            #pragma unroll
            for (int mi = 0; mi < 4; mi++) {
                uint32_t ra = (uint32_t)((warpM * 64 + mi * 16 + arow) * ROWB
                                         + k16 * 32 + aselB);
                LDMX4(ah[mi][0], ah[mi][1], ah[mi][2], ah[mi][3], base + ra);
                LDMX4(al[mi][0], al[mi][1], al[mi][2], al[mi][3], base + PLANE + ra);
            }
            // --- G ---
            #pragma unroll
            for (int gi = 0; gi < 2; gi++) {
                uint32_t rb = (uint32_t)((warpN * 32 + gi * 16 + brow) * ROWB
                                         + k16 * 32 + bselB);
                uint32_t x0, x1, x2, x3;
                LDMX4(x0, x1, x2, x3, base + 2 * PLANE + rb);
                b[gi*2][0]=x0; b[gi*2][1]=x1; b[gi*2+1][0]=x2; b[gi*2+1][1]=x3;
            }
            #pragma unroll
            for (int mi = 0; mi < 4; mi++)
                #pragma unroll
                for (int ni = 0; ni < 4; ni++) {
                    MMAH(accG[mi][ni], ah[mi], b[ni][0], b[ni][1]);
                    MMAH(accG[mi][ni], al[mi], b[ni][0], b[ni][1]);
                }
            // --- U ---
            #pragma unroll
            for (int gi = 0; gi < 2; gi++) {
                uint32_t rb = (uint32_t)((warpN * 32 + gi * 16 + brow) * ROWB
                                         + k16 * 32 + bselB);
                uint32_t x0, x1, x2, x3;
                LDMX4(x0, x1, x2, x3, base + 3 * PLANE + rb);
                b[gi*2][0]=x0; b[gi*2][1]=x1; b[gi*2+1][0]=x2; b[gi*2+1][1]=x3;
            }
            #pragma unroll
            for (int mi = 0; mi < 4; mi++)
                #pragma unroll
                for (int ni = 0; ni < 4; ni++) {
                    MMAH(accU[mi][ni], ah[mi], b[ni][0], b[ni][1]);
                    MMAH(accU[mi][ni], al[mi], b[ni][0], b[ni][1]);
                }
        }
    };

    const int nc = H / KCH;   // 16
    fill(0, 0);
    asm volatile("cp.async.commit_group;");

    for (int c = 0; c < nc; c++) {
        int s = c & 1;
        if (c + 1 < nc) {
            fill(c + 1, s ^ 1);
            asm volatile("cp.async.commit_group;");
            asm volatile("cp.async.wait_group 1;" ::: "memory");
        } else {
            asm volatile("cp.async.wait_group 0;" ::: "memory");
        }
        __syncthreads();
        compute(s);
        __syncthreads();
    }

    // epilogue: act = silu(G)*U -> fp16 hi/lo planes
    __half* Ah = shared_mode ? g_shacth : g_acth;
    __half* Al = shared_mode ? g_shactl : g_actl;
    int g = lane >> 2, tg = lane & 3;
    #pragma unroll
    for (int mi = 0; mi < 4; mi++) {
        int row = mbase + warpM * 64 + mi * 16 + g;
        #pragma unroll
        for (int ni = 0; ni < 4; ni++) {
            int col = nbase + warpN * 32 + ni * 8 + tg * 2;
            if (row < cnt) {
                float a0 = silu_fast(accG[mi][ni][0]) * accU[mi][ni][0];
                float a1 = silu_fast(accG[mi][ni][1]) * accU[mi][ni][1];
                uint32_t hi, lo;
                split2h(a0, a1, hi, lo);
                size_t off = (size_t)(r0 + row) * ID + col;
                *(uint32_t*)(Ah + off) = hi;
                *(uint32_t*)(Al + off) = lo;
            }
            if (row + 8 < cnt) {
                float a0 = silu_fast(accG[mi][ni][2]) * accU[mi][ni][2];
                float a1 = silu_fast(accG[mi][ni][3]) * accU[mi][ni][3];
                uint32_t hi, lo;
                split2h(a0, a1, hi, lo);
                size_t off = (size_t)(r0 + row + 8) * ID + col;
                *(uint32_t*)(Ah + off) = hi;
                *(uint32_t*)(Al + off) = lo;
            }
        }
    }
}

// ---------------- down GEMM (fp16 x2 emulation) -----------------------------
__global__ void __launch_bounds__(256)
mma_down(int shared_mode, int rowsShared)
{
    extern __shared__ char sm[];

    int e = blockIdx.z;
    int r0, cnt;
    if (shared_mode) { r0 = 0; cnt = rowsShared; }
    else { r0 = g_offsets[e]; cnt = g_offsets[e + 1] - r0; }
    int mbase = blockIdx.y * 128;
    if (mbase >= cnt) return;
    int nbase = blockIdx.x * 128;

    const size_t NK = (size_t)H * ID;
    const __half* Bd = (shared_mode ? g_psd : g_pwd) + (size_t)e * NK;
    const __half* Ahp = shared_mode ? g_shacth : g_acth;
    const __half* Alp = shared_mode ? g_shactl : g_actl;
    float* C = shared_mode ? g_shout : g_outs;

    int tid = threadIdx.x;
    int wid = tid >> 5, lane = tid & 31;
    int warpM = wid & 1, warpN = wid >> 1;

    uint32_t smbase = smem_u32(sm);

    auto fill = [&](int c, int s) {
        uint32_t st = smbase + s * STAGE_DN;
        #pragma unroll
        for (int j = 0; j < 12; j++) {
            int idx = j * 256 + tid;          // 3072: Ahi, Alo, B
            int plane = idx >> 10;
            int rem = idx & 1023;
            int row = rem >> 3, seg = rem & 7;
            const __half* src;
            if (plane == 0)
                src = Ahp + (size_t)(r0 + mbase + row) * ID + c * KCH + seg * 8;
            else if (plane == 1)
                src = Alp + (size_t)(r0 + mbase + row) * ID + c * KCH + seg * 8;
            else
                src = Bd + (size_t)(nbase + row) * ID + c * KCH + seg * 8;
            CP16(st + plane * PLANE + row * ROWB + seg * 16, src);
        }
    };

    float acc[4][4][4];
    #pragma unroll
    for (int a = 0; a < 4; a++)
        #pragma unroll
        for (int b = 0; b < 4; b++)
            #pragma unroll
            for (int cc = 0; cc < 4; cc++) acc[a][b][cc] = 0.f;

    int arow = (lane & 7) + ((lane >> 3) & 1) * 8;
    int aselB = (lane >> 4) * 16;
    int brow = (lane & 7) + (lane >> 4) * 8;
    int bselB = ((lane >> 3) & 1) * 16;

    auto compute = [&](int s) {
        uint32_t base = smbase + s * STAGE_DN;
        #pragma unroll
        for (int k16 = 0; k16 < 4; k16++) {
            uint32_t ah[4][4], al[4][4], b[4][2];
            #pragma unroll
            for (int mi = 0; mi < 4; mi++) {
                uint32_t ra = (uint32_t)((warpM * 64 + mi * 16 + arow) * ROWB
                                         + k16 * 32 + aselB);
                LDMX4(ah[mi][0], ah[mi][1], ah[mi][2], ah[mi][3], base + ra);
                LDMX4(al[mi][0], al[mi][1], al[mi][2], al[mi][3], base + PLANE + ra);
            }
            #pragma unroll
            for (int gi = 0; gi < 2; gi++) {
                uint32_t rb = (uint32_t)((warpN * 32 + gi * 16 + brow) * ROWB
                                         + k16 * 32 + bselB);
                uint32_t x0, x1, x2, x3;
                LDMX4(x0, x1, x2, x3, base + 2 * PLANE + rb);
                b[gi*2][0]=x0; b[gi*2][1]=x1; b[gi*2+1][0]=x2; b[gi*2+1][1]=x3;
            }
            #pragma unroll
            for (int mi = 0; mi < 4; mi++)
                #pragma unroll
                for (int ni = 0; ni < 4; ni++) {
                    MMAH(acc[mi][ni], ah[mi], b[ni][0], b[ni][1]);
                    MMAH(acc[mi][ni], al[mi], b[ni][0], b[ni][1]);
                }
        }
    };

    const int nc = ID / KCH;    // 8
    fill(0, 0);
    asm volatile("cp.async.commit_group;");

    for (int c = 0; c < nc; c++) {
        int s = c & 1;
        if (c + 1 < nc) {
            fill(c + 1, s ^ 1);
            asm volatile("cp.async.commit_group;");
            asm volatile("cp.async.wait_group 1;" ::: "memory");
        } else {
            asm volatile("cp.async.wait_group 0;" ::: "memory");
        }
        __syncthreads();
        compute(s);
        __syncthreads();
    }

    int g = lane >> 2, tg = lane & 3;
    #pragma unroll
    for (int mi = 0; mi < 4; mi++) {
        int row = mbase + warpM * 64 + mi * 16 + g;
        #pragma unroll
        for (int ni = 0; ni < 4; ni++) {
            int col = nbase + warpN * 32 + ni * 8 + tg * 2;
            if (row < cnt)
                *(float2*)(C + (size_t)(r0 + row) * H + col)
                    = make_float2(acc[mi][ni][0], acc[mi][ni][1]);
            if (row + 8 < cnt)
                *(float2*)(C + (size_t)(r0 + row + 8) * H + col)
                    = make_float2(acc[mi][ni][2], acc[mi][ni][3]);
        }
    }
}

// ---------------- combine ---------------------------------------------------
__global__ void __launch_bounds__(256)
combine_kernel(float* __restrict__ Y)
{
    int t = blockIdx.x;
    __shared__ float w[TK];
    __shared__ int   p[TK];
    if (threadIdx.x < TK) {
        w[threadIdx.x] = g_tw[t * TK + threadIdx.x];
        p[threadIdx.x] = g_pos[t * TK + threadIdx.x];
    }
    __syncthreads();
    int c = threadIdx.x * 4;
    float4 acc = *(const float4*)(g_shout + (size_t)t * H + c);
    #pragma unroll
    for (int k = 0; k < TK; k++) {
        float4 v = *(const float4*)(g_outs + (size_t)p[k] * H + c);
        acc.x += w[k] * v.x; acc.y += w[k] * v.y;
        acc.z += w[k] * v.z; acc.w += w[k] * v.w;
    }
    *(float4*)(Y + (size_t)t * H + c) = acc;
}

__global__ void fill_zero(float* p, long long n) {
    long long i = (long long)blockIdx.x * 256 + threadIdx.x;
    if (i < n) p[i] = 0.f;
}

// ---------------- launch -----------------------------------------------------
extern "C" void kernel_launch(void* const* d_in, const int* in_sizes, int n_in,
                              void* d_out, int out_size)
{
    const float* x   = (const float*)d_in[0];
    const float* gw  = (const float*)d_in[1];
    const float* eb  = (const float*)d_in[2];
    const float* wg  = (const float*)d_in[3];
    const float* wu  = (const float*)d_in[4];
    const float* wd  = (const float*)d_in[5];
    const float* wsg = (const float*)d_in[6];
    const float* wsu = (const float*)d_in[7];
    const float* wsd = (const float*)d_in[8];
    float* out = (float*)d_out;

    int T = in_sizes[0] / H;
    int N = T * TK;
    int MT = (T + 127) / 128;

    long long oL = (long long)T * H;
    long long oK = oL + (long long)T * NE;
    long long oEnd = oK + (long long)T * TK;

    float* outLogits = ((long long)out_size >= oK)   ? (out + oL) : nullptr;
    float* outTopkF  = ((long long)out_size >= oEnd) ? (out + oK) : nullptr;
    long long written = ((long long)out_size >= oEnd) ? oEnd
                       : ((long long)out_size >= oK) ? oK
                       : oL;

    cudaFuncSetAttribute(mma_gateup, cudaFuncAttributeMaxDynamicSharedMemorySize, SMEM_GU);
    cudaFuncSetAttribute(mma_down,   cudaFuncAttributeMaxDynamicSharedMemorySize, SMEM_DN);

    // launches 0-3: put shared-expert gateup GEMM in the profiled slot (4th)
    prep_x<<<(unsigned)(((long long)T * H / 4 + 255) / 256), 256>>>(x, (long long)T * H / 4);
    prep_kernel<<<dim3(H / 64,  ID / 128, 1),  256>>>(wsg, H, ID, 3);
    prep_kernel<<<dim3(H / 64,  ID / 128, 1),  256>>>(wsu, H, ID, 4);
    mma_gateup<<<dim3(ID / 128, MT, 1), 256, SMEM_GU>>>(1, T);
    prep_kernel<<<dim3(ID / 64, H / 128,  1),  256>>>(wsd, ID, H, 5);
    mma_down  <<<dim3(H / 128,  MT, 1), 256, SMEM_DN>>>(1, T);

    // routing
    init_kernel<<<1, 32>>>();
    gate_kernel<<<T, 128>>>(x, gw, eb, outLogits, outTopkF);
    scan_kernel<<<1, 1>>>();
    scatter_kernel<<<(N + 255) / 256, 256>>>(N);

    // routed expert weights + GEMMs
    prep_kernel<<<dim3(H / 64,  ID / 128, NE), 256>>>(wg,  H, ID, 0);
    prep_kernel<<<dim3(H / 64,  ID / 128, NE), 256>>>(wu,  H, ID, 1);
    prep_kernel<<<dim3(ID / 64, H / 128,  NE), 256>>>(wd,  ID, H, 2);
    mma_gateup<<<dim3(ID / 128, MT, NE), 256, SMEM_GU>>>(0, 0);
    mma_down  <<<dim3(H / 128,  MT, NE), 256, SMEM_DN>>>(0, 0);

    combine_kernel<<<T, 256>>>(out);

    if ((long long)out_size > written) {
        long long rest = (long long)out_size - written;
        fill_zero<<<(unsigned)((rest + 255) / 256), 256>>>(out + written, rest);
    }
}

// round 7
// speedup vs baseline: 2.8487x; 1.0680x over previous
#include <cuda_runtime.h>
#include <cuda_fp16.h>
#include <math.h>
#include <stdint.h>

#define H   1024
#define ID  512
#define NE  32
#define TK  4
#define MAXT 4096
#define MAXN (MAXT*TK)
#define RSCALE 2.5f

#define TILE_E   8192          // elems per 128x64 fp16 tile
#define TILE_B   16384         // bytes per tile
#define NT_X     160           // max row-tiles for padded sorted rows (20480/128)
#define NT_SH    32            // T/128
#define KC_GU    16            // H/64
#define KC_DN    8             // ID/64
#define TN_GU    4             // ID/128
#define TN_DN    8             // H/128

#define NST_GU   3
#define NST_DN   4
#define STAGE_GU 65536         // Ah,Al,Bg,Bu
#define STAGE_DN 49152         // Ah,Al,B
#define SMEM_GU  (NST_GU*STAGE_GU)   // 196608
#define SMEM_DN  (NST_DN*STAGE_DN)   // 196608

// ---------------- scratch (device globals; referenced ONLY in device code) --
__device__ float g_outs[(size_t)NT_X * 128 * H];
__device__ float g_shout[(size_t)MAXT * H];
__device__ float g_tw[MAXT * TK];
__device__ int   g_topk[MAXT * TK];
__device__ int   g_counts[NE];
__device__ int   g_offsets[NE + 1];
__device__ int   g_cursor[NE];
__device__ int   g_rowmap[NT_X * 128];
__device__ int   g_pos[MAXN];

// tiled fp16 planes: [tile][kc][8192] swizzled
__device__ __align__(16) __half g_xsh[(size_t)NT_X * KC_GU * TILE_E];
__device__ __align__(16) __half g_xsl[(size_t)NT_X * KC_GU * TILE_E];
__device__ __align__(16) __half g_sxh[(size_t)NT_SH * KC_GU * TILE_E];
__device__ __align__(16) __half g_sxl[(size_t)NT_SH * KC_GU * TILE_E];
__device__ __align__(16) __half g_acth[(size_t)NT_X * KC_DN * TILE_E];
__device__ __align__(16) __half g_actl[(size_t)NT_X * KC_DN * TILE_E];
__device__ __align__(16) __half g_sacth[(size_t)NT_SH * KC_DN * TILE_E];
__device__ __align__(16) __half g_sactl[(size_t)NT_SH * KC_DN * TILE_E];

// tiled weights [e][nt][kc][8192]
__device__ __align__(16) __half g_pwg[(size_t)NE * TN_GU * KC_GU * TILE_E];
__device__ __align__(16) __half g_pwu[(size_t)NE * TN_GU * KC_GU * TILE_E];
__device__ __align__(16) __half g_pwd[(size_t)NE * TN_DN * KC_DN * TILE_E];
__device__ __align__(16) __half g_psg[(size_t)TN_GU * KC_GU * TILE_E];
__device__ __align__(16) __half g_psu[(size_t)TN_GU * KC_GU * TILE_E];
__device__ __align__(16) __half g_psd[(size_t)TN_DN * KC_DN * TILE_E];

// ---------------- helpers ----------------------------------------------
__device__ __forceinline__ uint32_t smem_u32(const void* p) {
    return (uint32_t)__cvta_generic_to_shared(p);
}
__device__ __forceinline__ uint32_t swz(uint32_t b) { return b ^ ((b >> 3) & 0x70); }
__device__ __forceinline__ uint32_t packh(__half a, __half b) {
    return (uint32_t)(*(uint16_t*)&a) | ((uint32_t)(*(uint16_t*)&b) << 16);
}
__device__ __forceinline__ void split2h(float v0, float v1, uint32_t& hi, uint32_t& lo) {
    __half h0 = __float2half_rn(v0), h1 = __float2half_rn(v1);
    float r0 = v0 - __half2float(h0), r1 = v1 - __half2float(h1);
    hi = packh(h0, h1);
    lo = packh(__float2half_rn(r0), __float2half_rn(r1));
}
__device__ __forceinline__ float silu_fast(float g) { return g / (1.f + __expf(-g)); }

__device__ __forceinline__ void mbar_init(uint32_t a, uint32_t cnt) {
    asm volatile("mbarrier.init.shared.b64 [%0], %1;" :: "r"(a), "r"(cnt) : "memory");
}
__device__ __forceinline__ void mbar_arrive(uint32_t a) {
    asm volatile("mbarrier.arrive.shared.b64 _, [%0];" :: "r"(a) : "memory");
}
__device__ __forceinline__ void mbar_expect(uint32_t a, uint32_t bytes) {
    asm volatile("mbarrier.arrive.expect_tx.shared.b64 _, [%0], %1;"
                 :: "r"(a), "r"(bytes) : "memory");
}
__device__ __forceinline__ void mbar_wait(uint32_t a, uint32_t ph) {
    asm volatile(
        "{\n\t.reg .pred P;\n\t"
        "W_%=:\n\t"
        "mbarrier.try_wait.parity.acquire.cta.shared::cta.b64 P, [%0], %1, 0x989680;\n\t"
        "@P bra D_%=;\n\t"
        "bra W_%=;\n\t"
        "D_%=:\n\t}"
        :: "r"(a), "r"(ph) : "memory");
}
#define TMA_BULK(dst, src, bytes, mbar) \
    asm volatile("cp.async.bulk.shared::cta.global.mbarrier::complete_tx::bytes " \
                 "[%0], [%1], %2, [%3];" \
                 :: "r"(dst), "l"(src), "r"(bytes), "r"(mbar) : "memory")

#define LDMX4(r0_,r1_,r2_,r3_,addr) \
    asm volatile("ldmatrix.sync.aligned.m8n8.x4.shared.b16 {%0,%1,%2,%3}, [%4];" \
        : "=r"(r0_), "=r"(r1_), "=r"(r2_), "=r"(r3_) : "r"(addr))

#define MMAH(c_, a_, b0_, b1_) \
    asm volatile("mma.sync.aligned.m16n8k16.row.col.f32.f16.f16.f32 " \
        "{%0,%1,%2,%3}, {%4,%5,%6,%7}, {%8,%9}, {%0,%1,%2,%3};" \
        : "+f"((c_)[0]), "+f"((c_)[1]), "+f"((c_)[2]), "+f"((c_)[3]) \
        : "r"((a_)[0]), "r"((a_)[1]), "r"((a_)[2]), "r"((a_)[3]), \
          "r"(b0_), "r"(b1_))

// ---------------- init / routing -----------------------------------------
__global__ void init_kernel() {
    int i = threadIdx.x;
    if (i < NE) { g_counts[i] = 0; g_cursor[i] = 0; }
}

__global__ void __launch_bounds__(128)
gate_kernel(const float* __restrict__ X, const float* __restrict__ GW,
            const float* __restrict__ EB,
            float* outLogits, float* outTopkF)
{
    __shared__ __align__(16) float xs[H];
    __shared__ float sl[NE];
    __shared__ float ssc[NE];
    __shared__ float ssrt[NE];

    int t = blockIdx.x;
    const float* x = X + (size_t)t * H;
    for (int c = threadIdx.x; c < H; c += 128) xs[c] = x[c];
    __syncthreads();

    int e = threadIdx.x >> 2, q = threadIdx.x & 3;
    const float* w = GW + (size_t)e * H;
    float s = 0.f;
    int c0 = q * 256;
    #pragma unroll 8
    for (int c = c0; c < c0 + 256; c += 4) {
        float4 xv = *(const float4*)&xs[c];
        float4 wv = *(const float4*)(w + c);
        s += xv.x * wv.x + xv.y * wv.y + xv.z * wv.z + xv.w * wv.w;
    }
    s += __shfl_down_sync(0xffffffffu, s, 2);
    s += __shfl_down_sync(0xffffffffu, s, 1);
    if (q == 0) {
        sl[e] = s;
        if (outLogits) outLogits[(size_t)t * NE + e] = s;
    }
    __syncthreads();

    if (threadIdx.x < NE) {
        float v = sl[threadIdx.x];
        float sc = 1.f / (1.f + expf(-v));
        ssc[threadIdx.x] = sc;
        ssrt[threadIdx.x] = sc + EB[threadIdx.x];
    }
    __syncthreads();

    if (threadIdx.x == 0) {
        float gs[4];
        #pragma unroll
        for (int g = 0; g < 4; g++) {
            float m1 = -1e30f, m2 = -1e30f;
            #pragma unroll
            for (int j = 0; j < 8; j++) {
                float v = ssrt[g * 8 + j];
                if (v > m1) { m2 = m1; m1 = v; }
                else if (v > m2) { m2 = v; }
            }
            gs[g] = m1 + m2;
        }
        int g1 = 0;
        for (int g = 1; g < 4; g++) if (gs[g] > gs[g1]) g1 = g;
        int g2 = -1;
        for (int g = 0; g < 4; g++) {
            if (g == g1) continue;
            if (g2 < 0 || gs[g] > gs[g2]) g2 = g;
        }
        bool used[NE];
        #pragma unroll
        for (int i = 0; i < NE; i++) used[i] = false;
        int idx[TK]; float wts[TK]; float sum = 0.f;
        #pragma unroll
        for (int k = 0; k < TK; k++) {
            int best = -1; float bv = -1e30f;
            for (int i = 0; i < NE; i++) {
                int grp = i >> 3;
                if (grp != g1 && grp != g2) continue;
                if (used[i]) continue;
                if (ssrt[i] > bv) { bv = ssrt[i]; best = i; }
            }
            used[best] = true;
            idx[k] = best;
            wts[k] = ssc[best];
            sum += wts[k];
        }
        float inv = RSCALE / (sum + 1e-20f);
        #pragma unroll
        for (int k = 0; k < TK; k++) {
            g_topk[t * TK + k] = idx[k];
            g_tw[t * TK + k]   = wts[k] * inv;
            if (outTopkF) outTopkF[t * TK + k] = (float)idx[k];
            atomicAdd(&g_counts[idx[k]], 1);
        }
    }
}

__global__ void scan_kernel() {
    if (threadIdx.x == 0) {
        int o = 0;
        for (int e = 0; e < NE; e++) {
            g_offsets[e] = o;
            o += (g_counts[e] + 127) & ~127;   // 128-aligned per expert
        }
        g_offsets[NE] = o;
    }
}

__global__ void scatter_kernel(int N) {
    int s = blockIdx.x * 256 + threadIdx.x;
    if (s >= N) return;
    int e = g_topk[s];
    int p = g_offsets[e] + atomicAdd(&g_cursor[e], 1);
    g_rowmap[p] = s;
    g_pos[s] = p;
}

// ---------------- gather X into tiled swizzled fp16 hi/lo -------------------
// mode 0: routed (sorted padded rows, rowmap); mode 1: shared (natural order)
__global__ void __launch_bounds__(256)
gather_x(const float* __restrict__ X, int mode, int T)
{
    int kc = blockIdx.x;
    int gt = blockIdx.y;
    __shared__ int stok[128];
    int total = mode ? T : g_offsets[NE];
    if (gt * 128 >= total) return;

    int tid = threadIdx.x;
    if (tid < 128) {
        int p = gt * 128 + tid;
        stok[tid] = mode ? p : (g_rowmap[p] >> 2);
    }
    __syncthreads();

    __half* dh = (mode ? g_sxh : g_xsh) + ((size_t)gt * KC_GU + kc) * TILE_E;
    __half* dl = (mode ? g_sxl : g_xsl) + ((size_t)gt * KC_GU + kc) * TILE_E;

    for (int i = tid; i < 128 * 16; i += 256) {
        int r = i >> 4, q = (i & 15) * 4;
        float4 v = *(const float4*)(X + (size_t)stok[r] * H + kc * 64 + q);
        uint32_t h0, l0, h1, l1;
        split2h(v.x, v.y, h0, l0);
        split2h(v.z, v.w, h1, l1);
        uint32_t b = swz((uint32_t)(r * 128 + q * 2));
        *(uint2*)((char*)dh + b) = make_uint2(h0, h1);
        *(uint2*)((char*)dl + b) = make_uint2(l0, l1);
    }
}

// ---------------- weight prep: W[k][n] f32 -> tiled swizzled fp16 -----------
__global__ void __launch_bounds__(256)
prep_kernel(const float* __restrict__ W, int K, int N, int which)
{
    __shared__ float sT[128][65];
    int kc = blockIdx.x, nt = blockIdx.y, e = blockIdx.z;
    int tiles_k = K >> 6, tiles_n = N >> 7;
    __half* pB =
        which == 0 ? g_pwg : which == 1 ? g_pwu : which == 2 ? g_pwd :
        which == 3 ? g_psg : which == 4 ? g_psu : g_psd;
    __half* dst = pB + ((size_t)(e * tiles_n + nt) * tiles_k + kc) * TILE_E;
    const float* src = W + ((size_t)e * K + (size_t)kc * 64) * N + (size_t)nt * 128;

    int tid = threadIdx.x;
    for (int i = tid; i < 64 * 32; i += 256) {
        int k = i >> 5, nf = (i & 31) * 4;
        float4 v = *(const float4*)(src + (size_t)k * N + nf);
        sT[nf + 0][k] = v.x; sT[nf + 1][k] = v.y;
        sT[nf + 2][k] = v.z; sT[nf + 3][k] = v.w;
    }
    __syncthreads();
    for (int i = tid; i < 128 * 16; i += 256) {
        int n = i >> 4, k4 = (i & 15) * 4;
        uint32_t a = packh(__float2half_rn(sT[n][k4]),     __float2half_rn(sT[n][k4 + 1]));
        uint32_t b = packh(__float2half_rn(sT[n][k4 + 2]), __float2half_rn(sT[n][k4 + 3]));
        uint32_t off = swz((uint32_t)(n * 128 + k4 * 2));
        *(uint2*)((char*)dst + off) = make_uint2(a, b);
    }
}

// ---------------- fused gate+up GEMM (fp16 x2, bulk-copy pipeline) ----------
__global__ void __launch_bounds__(256)
mma_gateup(int shared_mode, int rowsShared)
{
    extern __shared__ char sm[];
    __shared__ __align__(8) unsigned long long s_bar[2 * NST_GU]; // full[s], empty[s]

    int e = blockIdx.z;
    int r0, cnt;
    if (shared_mode) { r0 = 0; cnt = rowsShared; }
    else { r0 = g_offsets[e]; cnt = g_counts[e]; }
    int mbase = blockIdx.y * 128;
    if (mbase >= cnt) return;
    int nb = blockIdx.x;
    int gt = (r0 + mbase) >> 7;

    const __half* Ah = shared_mode ? g_sxh : g_xsh;
    const __half* Al = shared_mode ? g_sxl : g_xsl;
    const __half* Bg = (shared_mode ? g_psg : g_pwg)
        + (size_t)(shared_mode ? 0 : e) * TN_GU * KC_GU * TILE_E
        + (size_t)nb * KC_GU * TILE_E;
    const __half* Bu = (shared_mode ? g_psu : g_pwu)
        + (size_t)(shared_mode ? 0 : e) * TN_GU * KC_GU * TILE_E
        + (size_t)nb * KC_GU * TILE_E;

    int tid = threadIdx.x;
    int wid = tid >> 5, lane = tid & 31;
    int warpM = wid & 1, warpN = wid >> 1;
    uint32_t smbase = smem_u32(sm);
    uint32_t barb = smem_u32(&s_bar[0]);
    auto fullb  = [&](int s) { return barb + s * 8; };
    auto emptyb = [&](int s) { return barb + (NST_GU + s) * 8; };

    if (tid == 0) {
        for (int s = 0; s < NST_GU; s++) { mbar_init(fullb(s), 1); mbar_init(emptyb(s), 256); }
    }
    __syncthreads();

    auto issue = [&](int j) {
        int s = j % NST_GU;
        uint32_t st = smbase + s * STAGE_GU;
        mbar_expect(fullb(s), STAGE_GU);
        TMA_BULK(st,          (const char*)(Ah + ((size_t)gt * KC_GU + j) * TILE_E), TILE_B, fullb(s));
        TMA_BULK(st + 16384,  (const char*)(Al + ((size_t)gt * KC_GU + j) * TILE_E), TILE_B, fullb(s));
        TMA_BULK(st + 32768,  (const char*)(Bg + (size_t)j * TILE_E), TILE_B, fullb(s));
        TMA_BULK(st + 49152,  (const char*)(Bu + (size_t)j * TILE_E), TILE_B, fullb(s));
    };

    const int nc = KC_GU;
    if (tid == 0)
        for (int j = 0; j < NST_GU - 1; j++) issue(j);

    float accG[4][4][4], accU[4][4][4];
    #pragma unroll
    for (int a = 0; a < 4; a++)
        #pragma unroll
        for (int b = 0; b < 4; b++)
            #pragma unroll
            for (int cc = 0; cc < 4; cc++) { accG[a][b][cc] = 0.f; accU[a][b][cc] = 0.f; }

    int arow = (lane & 7) + ((lane >> 3) & 1) * 8;
    int aselB = (lane >> 4) * 16;
    int brow = (lane & 7) + (lane >> 4) * 8;
    int bselB = ((lane >> 3) & 1) * 16;

    for (int c = 0; c < nc; c++) {
        int s = c % NST_GU;
        if (tid == 0) {
            int j = c + NST_GU - 1;
            if (j < nc) {
                if (j >= NST_GU) mbar_wait(emptyb(j % NST_GU), (j / NST_GU - 1) & 1);
                issue(j);
            }
        }
        mbar_wait(fullb(s), (c / NST_GU) & 1);

        uint32_t base = smbase + s * STAGE_GU;
        #pragma unroll
        for (int k16 = 0; k16 < 4; k16++) {
            uint32_t ah[4][4], al4[4][4], b[4][2];
            #pragma unroll
            for (int mi = 0; mi < 4; mi++) {
                uint32_t off = (uint32_t)((warpM * 64 + mi * 16 + arow) * 128 + k16 * 32 + aselB);
                uint32_t sa = base + swz(off);
                LDMX4(ah[mi][0], ah[mi][1], ah[mi][2], ah[mi][3], sa);
                LDMX4(al4[mi][0], al4[mi][1], al4[mi][2], al4[mi][3], sa + 16384);
            }
            // --- G ---
            #pragma unroll
            for (int gi = 0; gi < 2; gi++) {
                uint32_t off = (uint32_t)((warpN * 32 + gi * 16 + brow) * 128 + k16 * 32 + bselB);
                uint32_t x0, x1, x2, x3;
                LDMX4(x0, x1, x2, x3, base + 32768 + swz(off));
                b[gi*2][0]=x0; b[gi*2][1]=x1; b[gi*2+1][0]=x2; b[gi*2+1][1]=x3;
            }
            #pragma unroll
            for (int mi = 0; mi < 4; mi++)
                #pragma unroll
                for (int ni = 0; ni < 4; ni++) {
                    MMAH(accG[mi][ni], ah[mi], b[ni][0], b[ni][1]);
                    MMAH(accG[mi][ni], al4[mi], b[ni][0], b[ni][1]);
                }
            // --- U ---
            #pragma unroll
            for (int gi = 0; gi < 2; gi++) {
                uint32_t off = (uint32_t)((warpN * 32 + gi * 16 + brow) * 128 + k16 * 32 + bselB);
                uint32_t x0, x1, x2, x3;
                LDMX4(x0, x1, x2, x3, base + 49152 + swz(off));
                b[gi*2][0]=x0; b[gi*2][1]=x1; b[gi*2+1][0]=x2; b[gi*2+1][1]=x3;
            }
            #pragma unroll
            for (int mi = 0; mi < 4; mi++)
                #pragma unroll
                for (int ni = 0; ni < 4; ni++) {
                    MMAH(accU[mi][ni], ah[mi], b[ni][0], b[ni][1]);
                    MMAH(accU[mi][ni], al4[mi], b[ni][0], b[ni][1]);
                }
        }
        mbar_arrive(emptyb(s));
    }

    // epilogue: act = silu(G)*U -> tiled swizzled fp16 hi/lo for down GEMM
    __half* Dh = shared_mode ? g_sacth : g_acth;
    __half* Dl = shared_mode ? g_sactl : g_actl;
    int g = lane >> 2, tg = lane & 3;
    #pragma unroll
    for (int mi = 0; mi < 4; mi++) {
        #pragma unroll
        for (int ni = 0; ni < 4; ni++) {
            int cl = warpN * 32 + ni * 8 + tg * 2;
            int gcol = nb * 128 + cl;
            int kcd = gcol >> 6, cc = gcol & 63;
            char* th = (char*)(Dh + ((size_t)gt * KC_DN + kcd) * TILE_E);
            char* tl = (char*)(Dl + ((size_t)gt * KC_DN + kcd) * TILE_E);
            #pragma unroll
            for (int half8 = 0; half8 < 2; half8++) {
                int rl = warpM * 64 + mi * 16 + g + half8 * 8;
                if (mbase + rl >= cnt) continue;
                float a0 = silu_fast(accG[mi][ni][half8*2])   * accU[mi][ni][half8*2];
                float a1 = silu_fast(accG[mi][ni][half8*2+1]) * accU[mi][ni][half8*2+1];
                uint32_t hi, lo;
                split2h(a0, a1, hi, lo);
                uint32_t b = swz((uint32_t)(rl * 128 + cc * 2));
                *(uint32_t*)(th + b) = hi;
                *(uint32_t*)(tl + b) = lo;
            }
        }
    }
}

// ---------------- down GEMM (fp16 x2, bulk-copy pipeline) --------------------
__global__ void __launch_bounds__(256)
mma_down(int shared_mode, int rowsShared)
{
    extern __shared__ char sm[];
    __shared__ __align__(8) unsigned long long s_bar[2 * NST_DN];

    int e = blockIdx.z;
    int r0, cnt;
    if (shared_mode) { r0 = 0; cnt = rowsShared; }
    else { r0 = g_offsets[e]; cnt = g_counts[e]; }
    int mbase = blockIdx.y * 128;
    if (mbase >= cnt) return;
    int nb = blockIdx.x;
    int gt = (r0 + mbase) >> 7;

    const __half* Ahp = shared_mode ? g_sacth : g_acth;
    const __half* Alp = shared_mode ? g_sactl : g_actl;
    const __half* Bd = (shared_mode ? g_psd : g_pwd)
        + (size_t)(shared_mode ? 0 : e) * TN_DN * KC_DN * TILE_E
        + (size_t)nb * KC_DN * TILE_E;
    float* C = shared_mode ? g_shout : g_outs;

    int tid = threadIdx.x;
    int wid = tid >> 5, lane = tid & 31;
    int warpM = wid & 1, warpN = wid >> 1;
    uint32_t smbase = smem_u32(sm);
    uint32_t barb = smem_u32(&s_bar[0]);
    auto fullb  = [&](int s) { return barb + s * 8; };
    auto emptyb = [&](int s) { return barb + (NST_DN + s) * 8; };

    if (tid == 0) {
        for (int s = 0; s < NST_DN; s++) { mbar_init(fullb(s), 1); mbar_init(emptyb(s), 256); }
    }
    __syncthreads();

    auto issue = [&](int j) {
        int s = j % NST_DN;
        uint32_t st = smbase + s * STAGE_DN;
        mbar_expect(fullb(s), STAGE_DN);
        TMA_BULK(st,         (const char*)(Ahp + ((size_t)gt * KC_DN + j) * TILE_E), TILE_B, fullb(s));
        TMA_BULK(st + 16384, (const char*)(Alp + ((size_t)gt * KC_DN + j) * TILE_E), TILE_B, fullb(s));
        TMA_BULK(st + 32768, (const char*)(Bd + (size_t)j * TILE_E), TILE_B, fullb(s));
    };

    const int nc = KC_DN;
    if (tid == 0)
        for (int j = 0; j < NST_DN - 1 && j < nc; j++) issue(j);

    float acc[4][4][4];
    #pragma unroll
    for (int a = 0; a < 4; a++)
        #pragma unroll
        for (int b = 0; b < 4; b++)
            #pragma unroll
            for (int cc = 0; cc < 4; cc++) acc[a][b][cc] = 0.f;

    int arow = (lane & 7) + ((lane >> 3) & 1) * 8;
    int aselB = (lane >> 4) * 16;
    int brow = (lane & 7) + (lane >> 4) * 8;
    int bselB = ((lane >> 3) & 1) * 16;

    for (int c = 0; c < nc; c++) {
        int s = c % NST_DN;
        if (tid == 0) {
            int j = c + NST_DN - 1;
            if (j < nc) {
                if (j >= NST_DN) mbar_wait(emptyb(j % NST_DN), (j / NST_DN - 1) & 1);
                issue(j);
            }
        }
        mbar_wait(fullb(s), (c / NST_DN) & 1);

        uint32_t base = smbase + s * STAGE_DN;
        #pragma unroll
        for (int k16 = 0; k16 < 4; k16++) {
            uint32_t ah[4][4], al4[4][4], b[4][2];
            #pragma unroll
            for (int mi = 0; mi < 4; mi++) {
                uint32_t off = (uint32_t)((warpM * 64 + mi * 16 + arow) * 128 + k16 * 32 + aselB);
                uint32_t sa = base + swz(off);
                LDMX4(ah[mi][0], ah[mi][1], ah[mi][2], ah[mi][3], sa);
                LDMX4(al4[mi][0], al4[mi][1], al4[mi][2], al4[mi][3], sa + 16384);
            }
            #pragma unroll
            for (int gi = 0; gi < 2; gi++) {
                uint32_t off = (uint32_t)((warpN * 32 + gi * 16 + brow) * 128 + k16 * 32 + bselB);
                uint32_t x0, x1, x2, x3;
                LDMX4(x0, x1, x2, x3, base + 32768 + swz(off));
                b[gi*2][0]=x0; b[gi*2][1]=x1; b[gi*2+1][0]=x2; b[gi*2+1][1]=x3;
            }
            #pragma unroll
            for (int mi = 0; mi < 4; mi++)
                #pragma unroll
                for (int ni = 0; ni < 4; ni++) {
                    MMAH(acc[mi][ni], ah[mi], b[ni][0], b[ni][1]);
                    MMAH(acc[mi][ni], al4[mi], b[ni][0], b[ni][1]);
                }
        }
        mbar_arrive(emptyb(s));
    }

    int g = lane >> 2, tg = lane & 3;
    #pragma unroll
    for (int mi = 0; mi < 4; mi++) {
        int row = mbase + warpM * 64 + mi * 16 + g;
        #pragma unroll
        for (int ni = 0; ni < 4; ni++) {
            int col = nb * 128 + warpN * 32 + ni * 8 + tg * 2;
            if (row < cnt)
                *(float2*)(C + (size_t)(r0 + row) * H + col)
                    = make_float2(acc[mi][ni][0], acc[mi][ni][1]);
            if (row + 8 < cnt)
                *(float2*)(C + (size_t)(r0 + row + 8) * H + col)
                    = make_float2(acc[mi][ni][2], acc[mi][ni][3]);
        }
    }
}

// ---------------- combine ---------------------------------------------------
__global__ void __launch_bounds__(256)
combine_kernel(float* __restrict__ Y)
{
    int t = blockIdx.x;
    __shared__ float w[TK];
    __shared__ int   p[TK];
    if (threadIdx.x < TK) {
        w[threadIdx.x] = g_tw[t * TK + threadIdx.x];
        p[threadIdx.x] = g_pos[t * TK + threadIdx.x];
    }
    __syncthreads();
    int c = threadIdx.x * 4;
    float4 acc = *(const float4*)(g_shout + (size_t)t * H + c);
    #pragma unroll
    for (int k = 0; k < TK; k++) {
        float4 v = *(const float4*)(g_outs + (size_t)p[k] * H + c);
        acc.x += w[k] * v.x; acc.y += w[k] * v.y;
        acc.z += w[k] * v.z; acc.w += w[k] * v.w;
    }
    *(float4*)(Y + (size_t)t * H + c) = acc;
}

__global__ void fill_zero(float* p, long long n) {
    long long i = (long long)blockIdx.x * 256 + threadIdx.x;
    if (i < n) p[i] = 0.f;
}

// ---------------- launch -----------------------------------------------------
extern "C" void kernel_launch(void* const* d_in, const int* in_sizes, int n_in,
                              void* d_out, int out_size)
{
    const float* x   = (const float*)d_in[0];
    const float* gw  = (const float*)d_in[1];
    const float* eb  = (const float*)d_in[2];
    const float* wg  = (const float*)d_in[3];
    const float* wu  = (const float*)d_in[4];
    const float* wd  = (const float*)d_in[5];
    const float* wsg = (const float*)d_in[6];
    const float* wsu = (const float*)d_in[7];
    const float* wsd = (const float*)d_in[8];
    float* out = (float*)d_out;

    int T = in_sizes[0] / H;
    int N = T * TK;
    int MT = (T + 127) / 128;

    long long oL = (long long)T * H;
    long long oK = oL + (long long)T * NE;
    long long oEnd = oK + (long long)T * TK;

    float* outLogits = ((long long)out_size >= oK)   ? (out + oL) : nullptr;
    float* outTopkF  = ((long long)out_size >= oEnd) ? (out + oK) : nullptr;
    long long written = ((long long)out_size >= oEnd) ? oEnd
                       : ((long long)out_size >= oK) ? oK
                       : oL;

    cudaFuncSetAttribute(mma_gateup, cudaFuncAttributeMaxDynamicSharedMemorySize, SMEM_GU);
    cudaFuncSetAttribute(mma_down,   cudaFuncAttributeMaxDynamicSharedMemorySize, SMEM_DN);

    // shared-expert chain (gateup lands in the profiled launch slot)
    prep_kernel<<<dim3(KC_GU, TN_GU, 1), 256>>>(wsg, H, ID, 3);
    prep_kernel<<<dim3(KC_GU, TN_GU, 1), 256>>>(wsu, H, ID, 4);
    gather_x<<<dim3(KC_GU, NT_SH), 256>>>(x, 1, T);
    mma_gateup<<<dim3(TN_GU, MT, 1), 256, SMEM_GU>>>(1, T);
    prep_kernel<<<dim3(KC_DN, TN_DN, 1), 256>>>(wsd, ID, H, 5);
    mma_down<<<dim3(TN_DN, MT, 1), 256, SMEM_DN>>>(1, T);

    // routing
    init_kernel<<<1, 32>>>();
    gate_kernel<<<T, 128>>>(x, gw, eb, outLogits, outTopkF);
    scan_kernel<<<1, 1>>>();
    scatter_kernel<<<(N + 255) / 256, 256>>>(N);
    gather_x<<<dim3(KC_GU, NT_X), 256>>>(x, 0, T);

    // routed expert weights + GEMMs
    prep_kernel<<<dim3(KC_GU, TN_GU, NE), 256>>>(wg, H, ID, 0);
    prep_kernel<<<dim3(KC_GU, TN_GU, NE), 256>>>(wu, H, ID, 1);
    prep_kernel<<<dim3(KC_DN, TN_DN, NE), 256>>>(wd, ID, H, 2);
    mma_gateup<<<dim3(TN_GU, MT, NE), 256, SMEM_GU>>>(0, 0);
    mma_down<<<dim3(TN_DN, MT, NE), 256, SMEM_DN>>>(0, 0);

    combine_kernel<<<T, 256>>>(out);

    if ((long long)out_size > written) {
        long long rest = (long long)out_size - written;
        fill_zero<<<(unsigned)((rest + 255) / 256), 256>>>(out + written, rest);
    }
}

// round 8
// speedup vs baseline: 2.9919x; 1.0503x over previous
#include <cuda_runtime.h>
#include <cuda_fp16.h>
#include <math.h>
#include <stdint.h>

#define H   1024
#define ID  512
#define NE  32
#define TK  4
#define MAXT 4096
#define MAXN (MAXT*TK)
#define RSCALE 2.5f

#define TILE_E   8192          // elems per 128x64 fp16 tile
#define TILE_B   16384         // bytes per tile
#define NT_X     160           // row-tiles for padded sorted rows (20480/128)
#define NT_SH    32            // T/128
#define KC_GU    16            // H/64
#define KC_DN    8             // ID/64
#define TN_GU    4             // ID/128
#define TN_DN    8             // H/128

#define NST_GU   3
#define NST_DN   4
#define STAGE_GU 65536         // Ah,Al,Bg,Bu
#define STAGE_DN 49152         // Ah,Al,B
#define SMEM_GU  (NST_GU*STAGE_GU)   // 196608
#define SMEM_DN  (NST_DN*STAGE_DN)   // 196608

// ---------------- scratch (device globals; referenced ONLY in device code) --
__device__ float g_outs[(size_t)NT_X * 128 * H];
__device__ float g_shout[(size_t)MAXT * H];
__device__ float g_tw[MAXT * TK];
__device__ int   g_topk[MAXT * TK];
__device__ int   g_counts[NE];
__device__ int   g_offsets[NE + 1];
__device__ int   g_cursor[NE];
__device__ int   g_rowmap[NT_X * 128];
__device__ int   g_pos[MAXN];

// tiled fp16 planes: [tile][kc][8192] swizzled
__device__ __align__(16) __half g_xsh[(size_t)NT_X * KC_GU * TILE_E];
__device__ __align__(16) __half g_xsl[(size_t)NT_X * KC_GU * TILE_E];
__device__ __align__(16) __half g_sxh[(size_t)NT_SH * KC_GU * TILE_E];
__device__ __align__(16) __half g_sxl[(size_t)NT_SH * KC_GU * TILE_E];
__device__ __align__(16) __half g_acth[(size_t)NT_X * KC_DN * TILE_E];
__device__ __align__(16) __half g_actl[(size_t)NT_X * KC_DN * TILE_E];
__device__ __align__(16) __half g_sacth[(size_t)NT_SH * KC_DN * TILE_E];
__device__ __align__(16) __half g_sactl[(size_t)NT_SH * KC_DN * TILE_E];

// tiled weights [e][nt][kc][8192]
__device__ __align__(16) __half g_pwg[(size_t)NE * TN_GU * KC_GU * TILE_E];
__device__ __align__(16) __half g_pwu[(size_t)NE * TN_GU * KC_GU * TILE_E];
__device__ __align__(16) __half g_pwd[(size_t)NE * TN_DN * KC_DN * TILE_E];
__device__ __align__(16) __half g_psg[(size_t)TN_GU * KC_GU * TILE_E];
__device__ __align__(16) __half g_psu[(size_t)TN_GU * KC_GU * TILE_E];
__device__ __align__(16) __half g_psd[(size_t)TN_DN * KC_DN * TILE_E];

// ---------------- helpers ----------------------------------------------
__device__ __forceinline__ uint32_t smem_u32(const void* p) {
    return (uint32_t)__cvta_generic_to_shared(p);
}
__device__ __forceinline__ uint32_t swz(uint32_t b) { return b ^ ((b >> 3) & 0x70); }
__device__ __forceinline__ uint32_t packh(__half a, __half b) {
    return (uint32_t)(*(uint16_t*)&a) | ((uint32_t)(*(uint16_t*)&b) << 16);
}
__device__ __forceinline__ void split2h(float v0, float v1, uint32_t& hi, uint32_t& lo) {
    __half h0 = __float2half_rn(v0), h1 = __float2half_rn(v1);
    float r0 = v0 - __half2float(h0), r1 = v1 - __half2float(h1);
    hi = packh(h0, h1);
    lo = packh(__float2half_rn(r0), __float2half_rn(r1));
}
__device__ __forceinline__ float silu_fast(float g) { return g / (1.f + __expf(-g)); }

__device__ __forceinline__ void mbar_init(uint32_t a, uint32_t cnt) {
    asm volatile("mbarrier.init.shared.b64 [%0], %1;" :: "r"(a), "r"(cnt) : "memory");
}
__device__ __forceinline__ void mbar_arrive(uint32_t a) {
    asm volatile("mbarrier.arrive.shared.b64 _, [%0];" :: "r"(a) : "memory");
}
__device__ __forceinline__ void mbar_expect(uint32_t a, uint32_t bytes) {
    asm volatile("mbarrier.arrive.expect_tx.shared.b64 _, [%0], %1;"
                 :: "r"(a), "r"(bytes) : "memory");
}
__device__ __forceinline__ void mbar_wait(uint32_t a, uint32_t ph) {
    asm volatile(
        "{\n\t.reg .pred P;\n\t"
        "W_%=:\n\t"
        "mbarrier.try_wait.parity.acquire.cta.shared::cta.b64 P, [%0], %1, 0x989680;\n\t"
        "@P bra D_%=;\n\t"
        "bra W_%=;\n\t"
        "D_%=:\n\t}"
        :: "r"(a), "r"(ph) : "memory");
}
#define TMA_BULK(dst, src, bytes, mbar) \
    asm volatile("cp.async.bulk.shared::cta.global.mbarrier::complete_tx::bytes " \
                 "[%0], [%1], %2, [%3];" \
                 :: "r"(dst), "l"(src), "r"(bytes), "r"(mbar) : "memory")

#define LDMX4(r0_,r1_,r2_,r3_,addr) \
    asm volatile("ldmatrix.sync.aligned.m8n8.x4.shared.b16 {%0,%1,%2,%3}, [%4];" \
        : "=r"(r0_), "=r"(r1_), "=r"(r2_), "=r"(r3_) : "r"(addr))

#define MMAH(c_, a_, b0_, b1_) \
    asm volatile("mma.sync.aligned.m16n8k16.row.col.f32.f16.f16.f32 " \
        "{%0,%1,%2,%3}, {%4,%5,%6,%7}, {%8,%9}, {%0,%1,%2,%3};" \
        : "+f"((c_)[0]), "+f"((c_)[1]), "+f"((c_)[2]), "+f"((c_)[3]) \
        : "r"((a_)[0]), "r"((a_)[1]), "r"((a_)[2]), "r"((a_)[3]), \
          "r"(b0_), "r"(b1_))

// ---------------- init / routing -----------------------------------------
__global__ void init_kernel() {
    int i = blockIdx.x * 256 + threadIdx.x;
    if (i < NE) { g_counts[i] = 0; g_cursor[i] = 0; }
    if (i < NT_X * 128) g_rowmap[i] = 0;
}

__global__ void __launch_bounds__(128)
gate_kernel(const float* __restrict__ X, const float* __restrict__ GW,
            const float* __restrict__ EB,
            float* outLogits, float* outTopkF)
{
    __shared__ __align__(16) float xs[H];
    __shared__ float sl[NE];
    __shared__ float ssc[NE];
    __shared__ float ssrt[NE];

    int t = blockIdx.x;
    const float* x = X + (size_t)t * H;
    for (int c = threadIdx.x; c < H; c += 128) xs[c] = x[c];
    __syncthreads();

    int e = threadIdx.x >> 2, q = threadIdx.x & 3;
    const float* w = GW + (size_t)e * H;
    float s = 0.f;
    int c0 = q * 256;
    #pragma unroll 8
    for (int c = c0; c < c0 + 256; c += 4) {
        float4 xv = *(const float4*)&xs[c];
        float4 wv = *(const float4*)(w + c);
        s += xv.x * wv.x + xv.y * wv.y + xv.z * wv.z + xv.w * wv.w;
    }
    s += __shfl_down_sync(0xffffffffu, s, 2);
    s += __shfl_down_sync(0xffffffffu, s, 1);
    if (q == 0) {
        sl[e] = s;
        if (outLogits) outLogits[(size_t)t * NE + e] = s;
    }
    __syncthreads();

    if (threadIdx.x < NE) {
        float v = sl[threadIdx.x];
        float sc = 1.f / (1.f + expf(-v));
        ssc[threadIdx.x] = sc;
        ssrt[threadIdx.x] = sc + EB[threadIdx.x];
    }
    __syncthreads();

    if (threadIdx.x == 0) {
        float gs[4];
        #pragma unroll
        for (int g = 0; g < 4; g++) {
            float m1 = -1e30f, m2 = -1e30f;
            #pragma unroll
            for (int j = 0; j < 8; j++) {
                float v = ssrt[g * 8 + j];
                if (v > m1) { m2 = m1; m1 = v; }
                else if (v > m2) { m2 = v; }
            }
            gs[g] = m1 + m2;
        }
        int g1 = 0;
        for (int g = 1; g < 4; g++) if (gs[g] > gs[g1]) g1 = g;
        int g2 = -1;
        for (int g = 0; g < 4; g++) {
            if (g == g1) continue;
            if (g2 < 0 || gs[g] > gs[g2]) g2 = g;
        }
        bool used[NE];
        #pragma unroll
        for (int i = 0; i < NE; i++) used[i] = false;
        int idx[TK]; float wts[TK]; float sum = 0.f;
        #pragma unroll
        for (int k = 0; k < TK; k++) {
            int best = -1; float bv = -1e30f;
            for (int i = 0; i < NE; i++) {
                int grp = i >> 3;
                if (grp != g1 && grp != g2) continue;
                if (used[i]) continue;
                if (ssrt[i] > bv) { bv = ssrt[i]; best = i; }
            }
            used[best] = true;
            idx[k] = best;
            wts[k] = ssc[best];
            sum += wts[k];
        }
        float inv = RSCALE / (sum + 1e-20f);
        #pragma unroll
        for (int k = 0; k < TK; k++) {
            g_topk[t * TK + k] = idx[k];
            g_tw[t * TK + k]   = wts[k] * inv;
            if (outTopkF) outTopkF[t * TK + k] = (float)idx[k];
            atomicAdd(&g_counts[idx[k]], 1);
        }
    }
}

__global__ void scan_kernel() {
    if (threadIdx.x == 0) {
        int o = 0;
        for (int e = 0; e < NE; e++) {
            g_offsets[e] = o;
            o += (g_counts[e] + 127) & ~127;   // 128-aligned per expert
        }
        g_offsets[NE] = o;
    }
}

__global__ void scatter_kernel(int N) {
    int s = blockIdx.x * 256 + threadIdx.x;
    if (s >= N) return;
    int e = g_topk[s];
    int p = g_offsets[e] + atomicAdd(&g_cursor[e], 1);
    g_rowmap[p] = s;
    g_pos[s] = p;
}

// ---------------- gather X into tiled swizzled fp16 hi/lo -------------------
// z=0: routed (sorted padded rows, rowmap); z=1: shared (natural order)
__global__ void __launch_bounds__(256)
gather_x(const float* __restrict__ X, int T)
{
    int kc = blockIdx.x;
    int gt = blockIdx.y;
    int mode = blockIdx.z;
    __shared__ int stok[128];
    int total = mode ? T : g_offsets[NE];
    if (gt * 128 >= total) return;

    int tid = threadIdx.x;
    if (tid < 128) {
        int p = gt * 128 + tid;
        stok[tid] = mode ? p : (g_rowmap[p] >> 2);
    }
    __syncthreads();

    __half* dh = (mode ? g_sxh : g_xsh) + ((size_t)gt * KC_GU + kc) * TILE_E;
    __half* dl = (mode ? g_sxl : g_xsl) + ((size_t)gt * KC_GU + kc) * TILE_E;

    for (int i = tid; i < 128 * 16; i += 256) {
        int r = i >> 4, q = (i & 15) * 4;
        float4 v = *(const float4*)(X + (size_t)stok[r] * H + kc * 64 + q);
        uint32_t h0, l0, h1, l1;
        split2h(v.x, v.y, h0, l0);
        split2h(v.z, v.w, h1, l1);
        uint32_t b = swz((uint32_t)(r * 128 + q * 2));
        *(uint2*)((char*)dh + b) = make_uint2(h0, h1);
        *(uint2*)((char*)dl + b) = make_uint2(l0, l1);
    }
}

// ---------------- weight prep core -----------------------------------------
__device__ __forceinline__ void prep_core(const float* src, int N, __half* dst)
{
    __shared__ float sT[128][65];
    int tid = threadIdx.x;
    for (int i = tid; i < 64 * 32; i += 256) {
        int k = i >> 5, nf = (i & 31) * 4;
        float4 v = *(const float4*)(src + (size_t)k * N + nf);
        sT[nf + 0][k] = v.x; sT[nf + 1][k] = v.y;
        sT[nf + 2][k] = v.z; sT[nf + 3][k] = v.w;
    }
    __syncthreads();
    for (int i = tid; i < 128 * 16; i += 256) {
        int n = i >> 4, k4 = (i & 15) * 4;
        uint32_t a = packh(__float2half_rn(sT[n][k4]),     __float2half_rn(sT[n][k4 + 1]));
        uint32_t b = packh(__float2half_rn(sT[n][k4 + 2]), __float2half_rn(sT[n][k4 + 3]));
        uint32_t off = swz((uint32_t)(n * 128 + k4 * 2));
        *(uint2*)((char*)dst + off) = make_uint2(a, b);
    }
}

// z: 0..NE-1 wg, NE..2NE-1 wu, 2NE wsg, 2NE+1 wsu
__global__ void __launch_bounds__(256)
prep_gu(const float* __restrict__ wg, const float* __restrict__ wu,
        const float* __restrict__ wsg, const float* __restrict__ wsu)
{
    int kc = blockIdx.x, nt = blockIdx.y, z = blockIdx.z;
    const float* W; __half* base; int e;
    if (z < NE)          { W = wg;  base = g_pwg; e = z; }
    else if (z < 2 * NE) { W = wu;  base = g_pwu; e = z - NE; }
    else if (z == 2*NE)  { W = wsg; base = g_psg; e = 0; }
    else                 { W = wsu; base = g_psu; e = 0; }
    const float* src = W + ((size_t)e * H + (size_t)kc * 64) * ID + (size_t)nt * 128;
    __half* dst = base + ((size_t)(e * TN_GU + nt) * KC_GU + kc) * TILE_E;
    prep_core(src, ID, dst);
}

// z: 0..NE-1 wd, NE wsd
__global__ void __launch_bounds__(256)
prep_dn(const float* __restrict__ wd, const float* __restrict__ wsd)
{
    int kc = blockIdx.x, nt = blockIdx.y, z = blockIdx.z;
    const float* W; __half* base; int e;
    if (z < NE) { W = wd;  base = g_pwd; e = z; }
    else        { W = wsd; base = g_psd; e = 0; }
    const float* src = W + ((size_t)e * ID + (size_t)kc * 64) * H + (size_t)nt * 128;
    __half* dst = base + ((size_t)(e * TN_DN + nt) * KC_DN + kc) * TILE_E;
    prep_core(src, H, dst);
}

// ---------------- fused gate+up GEMM (fp16 x2, 512 thr, bulk pipeline) ------
// z in [0, NE]: z==NE is the shared expert
__global__ void __launch_bounds__(512)
mma_gateup(int T)
{
    extern __shared__ char sm[];
    __shared__ __align__(8) unsigned long long s_bar[2 * NST_GU];

    int e = blockIdx.z;
    bool sh = (e == (int)gridDim.z - 1);
    int r0, cnt;
    if (sh) { r0 = 0; cnt = T; }
    else { r0 = g_offsets[e]; cnt = g_counts[e]; }
    int mbase = blockIdx.y * 128;
    if (mbase >= cnt) return;
    int nb = blockIdx.x;
    int gt = (r0 + mbase) >> 7;

    const __half* Ah = sh ? g_sxh : g_xsh;
    const __half* Al = sh ? g_sxl : g_xsl;
    const __half* Bg = (sh ? g_psg : g_pwg)
        + (size_t)(sh ? 0 : e) * TN_GU * KC_GU * TILE_E + (size_t)nb * KC_GU * TILE_E;
    const __half* Bu = (sh ? g_psu : g_pwu)
        + (size_t)(sh ? 0 : e) * TN_GU * KC_GU * TILE_E + (size_t)nb * KC_GU * TILE_E;

    int tid = threadIdx.x;
    int wid = tid >> 5, lane = tid & 31;
    int warpM = wid & 3, warpN = wid >> 2;
    uint32_t smbase = smem_u32(sm);
    uint32_t barb = smem_u32(&s_bar[0]);
    auto fullb  = [&](int s) { return barb + s * 8; };
    auto emptyb = [&](int s) { return barb + (NST_GU + s) * 8; };

    if (tid == 0)
        for (int s = 0; s < NST_GU; s++) { mbar_init(fullb(s), 1); mbar_init(emptyb(s), 16); }
    __syncthreads();

    auto issue = [&](int j) {
        int s = j % NST_GU;
        uint32_t st = smbase + s * STAGE_GU;
        mbar_expect(fullb(s), STAGE_GU);
        TMA_BULK(st,         (const char*)(Ah + ((size_t)gt * KC_GU + j) * TILE_E), TILE_B, fullb(s));
        TMA_BULK(st + 16384, (const char*)(Al + ((size_t)gt * KC_GU + j) * TILE_E), TILE_B, fullb(s));
        TMA_BULK(st + 32768, (const char*)(Bg + (size_t)j * TILE_E), TILE_B, fullb(s));
        TMA_BULK(st + 49152, (const char*)(Bu + (size_t)j * TILE_E), TILE_B, fullb(s));
    };

    if (tid == 0)
        for (int j = 0; j < NST_GU - 1; j++) issue(j);

    float accG[2][4][4], accU[2][4][4];
    #pragma unroll
    for (int a = 0; a < 2; a++)
        #pragma unroll
        for (int b = 0; b < 4; b++)
            #pragma unroll
            for (int cc = 0; cc < 4; cc++) { accG[a][b][cc] = 0.f; accU[a][b][cc] = 0.f; }

    int arow = (lane & 7) + ((lane >> 3) & 1) * 8;
    int aselB = (lane >> 4) * 16;
    int brow = (lane & 7) + (lane >> 4) * 8;
    int bselB = ((lane >> 3) & 1) * 16;

    const int nc = KC_GU;
    for (int c = 0; c < nc; c++) {
        int s = c % NST_GU;
        if (tid == 0) {
            int j = c + NST_GU - 1;
            if (j < nc) {
                if (j >= NST_GU) mbar_wait(emptyb(j % NST_GU), (j / NST_GU - 1) & 1);
                issue(j);
            }
        }
        mbar_wait(fullb(s), (c / NST_GU) & 1);

        uint32_t base = smbase + s * STAGE_GU;
        #pragma unroll
        for (int k16 = 0; k16 < 4; k16++) {
            uint32_t ah[2][4], al4[2][4], b[4][2];
            #pragma unroll
            for (int mi = 0; mi < 2; mi++) {
                uint32_t off = (uint32_t)((warpM * 32 + mi * 16 + arow) * 128 + k16 * 32 + aselB);
                uint32_t sa = base + swz(off);
                LDMX4(ah[mi][0], ah[mi][1], ah[mi][2], ah[mi][3], sa);
                LDMX4(al4[mi][0], al4[mi][1], al4[mi][2], al4[mi][3], sa + 16384);
            }
            // --- G ---
            #pragma unroll
            for (int gi = 0; gi < 2; gi++) {
                uint32_t off = (uint32_t)((warpN * 32 + gi * 16 + brow) * 128 + k16 * 32 + bselB);
                uint32_t x0, x1, x2, x3;
                LDMX4(x0, x1, x2, x3, base + 32768 + swz(off));
                b[gi*2][0]=x0; b[gi*2][1]=x1; b[gi*2+1][0]=x2; b[gi*2+1][1]=x3;
            }
            #pragma unroll
            for (int mi = 0; mi < 2; mi++)
                #pragma unroll
                for (int ni = 0; ni < 4; ni++) {
                    MMAH(accG[mi][ni], ah[mi], b[ni][0], b[ni][1]);
                    MMAH(accG[mi][ni], al4[mi], b[ni][0], b[ni][1]);
                }
            // --- U ---
            #pragma unroll
            for (int gi = 0; gi < 2; gi++) {
                uint32_t off = (uint32_t)((warpN * 32 + gi * 16 + brow) * 128 + k16 * 32 + bselB);
                uint32_t x0, x1, x2, x3;
                LDMX4(x0, x1, x2, x3, base + 49152 + swz(off));
                b[gi*2][0]=x0; b[gi*2][1]=x1; b[gi*2+1][0]=x2; b[gi*2+1][1]=x3;
            }
            #pragma unroll
            for (int mi = 0; mi < 2; mi++)
                #pragma unroll
                for (int ni = 0; ni < 4; ni++) {
                    MMAH(accU[mi][ni], ah[mi], b[ni][0], b[ni][1]);
                    MMAH(accU[mi][ni], al4[mi], b[ni][0], b[ni][1]);
                }
        }
        __syncwarp();
        if (lane == 0) mbar_arrive(emptyb(s));
    }

    // epilogue: act = silu(G)*U -> tiled swizzled fp16 hi/lo for down GEMM
    __half* Dh = sh ? g_sacth : g_acth;
    __half* Dl = sh ? g_sactl : g_actl;
    int g = lane >> 2, tg = lane & 3;
    #pragma unroll
    for (int mi = 0; mi < 2; mi++) {
        #pragma unroll
        for (int ni = 0; ni < 4; ni++) {
            int cl = warpN * 32 + ni * 8 + tg * 2;
            int gcol = nb * 128 + cl;
            int kcd = gcol >> 6, cc = gcol & 63;
            char* th = (char*)(Dh + ((size_t)gt * KC_DN + kcd) * TILE_E);
            char* tl = (char*)(Dl + ((size_t)gt * KC_DN + kcd) * TILE_E);
            #pragma unroll
            for (int half8 = 0; half8 < 2; half8++) {
                int rl = warpM * 32 + mi * 16 + g + half8 * 8;
                if (mbase + rl >= cnt) continue;
                float a0 = silu_fast(accG[mi][ni][half8*2])   * accU[mi][ni][half8*2];
                float a1 = silu_fast(accG[mi][ni][half8*2+1]) * accU[mi][ni][half8*2+1];
                uint32_t hi, lo;
                split2h(a0, a1, hi, lo);
                uint32_t b = swz((uint32_t)(rl * 128 + cc * 2));
                *(uint32_t*)(th + b) = hi;
                *(uint32_t*)(tl + b) = lo;
            }
        }
    }
}

// ---------------- down GEMM (fp16 x2, 512 thr, bulk pipeline) ----------------
__global__ void __launch_bounds__(512)
mma_down(int T)
{
    extern __shared__ char sm[];
    __shared__ __align__(8) unsigned long long s_bar[2 * NST_DN];

    int e = blockIdx.z;
    bool sh = (e == (int)gridDim.z - 1);
    int r0, cnt;
    if (sh) { r0 = 0; cnt = T; }
    else { r0 = g_offsets[e]; cnt = g_counts[e]; }
    int mbase = blockIdx.y * 128;
    if (mbase >= cnt) return;
    int nb = blockIdx.x;
    int gt = (r0 + mbase) >> 7;

    const __half* Ahp = sh ? g_sacth : g_acth;
    const __half* Alp = sh ? g_sactl : g_actl;
    const __half* Bd = (sh ? g_psd : g_pwd)
        + (size_t)(sh ? 0 : e) * TN_DN * KC_DN * TILE_E + (size_t)nb * KC_DN * TILE_E;
    float* C = sh ? g_shout : g_outs;

    int tid = threadIdx.x;
    int wid = tid >> 5, lane = tid & 31;
    int warpM = wid & 3, warpN = wid >> 2;
    uint32_t smbase = smem_u32(sm);
    uint32_t barb = smem_u32(&s_bar[0]);
    auto fullb  = [&](int s) { return barb + s * 8; };
    auto emptyb = [&](int s) { return barb + (NST_DN + s) * 8; };

    if (tid == 0)
        for (int s = 0; s < NST_DN; s++) { mbar_init(fullb(s), 1); mbar_init(emptyb(s), 16); }
    __syncthreads();

    auto issue = [&](int j) {
        int s = j % NST_DN;
        uint32_t st = smbase + s * STAGE_DN;
        mbar_expect(fullb(s), STAGE_DN);
        TMA_BULK(st,         (const char*)(Ahp + ((size_t)gt * KC_DN + j) * TILE_E), TILE_B, fullb(s));
        TMA_BULK(st + 16384, (const char*)(Alp + ((size_t)gt * KC_DN + j) * TILE_E), TILE_B, fullb(s));
        TMA_BULK(st + 32768, (const char*)(Bd + (size_t)j * TILE_E), TILE_B, fullb(s));
    };

    const int nc = KC_DN;
    if (tid == 0)
        for (int j = 0; j < NST_DN - 1 && j < nc; j++) issue(j);

    float acc[2][4][4];
    #pragma unroll
    for (int a = 0; a < 2; a++)
        #pragma unroll
        for (int b = 0; b < 4; b++)
            #pragma unroll
            for (int cc = 0; cc < 4; cc++) acc[a][b][cc] = 0.f;

    int arow = (lane & 7) + ((lane >> 3) & 1) * 8;
    int aselB = (lane >> 4) * 16;
    int brow = (lane & 7) + (lane >> 4) * 8;
    int bselB = ((lane >> 3) & 1) * 16;

    for (int c = 0; c < nc; c++) {
        int s = c % NST_DN;
        if (tid == 0) {
            int j = c + NST_DN - 1;
            if (j < nc) {
                if (j >= NST_DN) mbar_wait(emptyb(j % NST_DN), (j / NST_DN - 1) & 1);
                issue(j);
            }
        }
        mbar_wait(fullb(s), (c / NST_DN) & 1);

        uint32_t base = smbase + s * STAGE_DN;
        #pragma unroll
        for (int k16 = 0; k16 < 4; k16++) {
            uint32_t ah[2][4], al4[2][4], b[4][2];
            #pragma unroll
            for (int mi = 0; mi < 2; mi++) {
                uint32_t off = (uint32_t)((warpM * 32 + mi * 16 + arow) * 128 + k16 * 32 + aselB);
                uint32_t sa = base + swz(off);
                LDMX4(ah[mi][0], ah[mi][1], ah[mi][2], ah[mi][3], sa);
                LDMX4(al4[mi][0], al4[mi][1], al4[mi][2], al4[mi][3], sa + 16384);
            }
            #pragma unroll
            for (int gi = 0; gi < 2; gi++) {
                uint32_t off = (uint32_t)((warpN * 32 + gi * 16 + brow) * 128 + k16 * 32 + bselB);
                uint32_t x0, x1, x2, x3;
                LDMX4(x0, x1, x2, x3, base + 32768 + swz(off));
                b[gi*2][0]=x0; b[gi*2][1]=x1; b[gi*2+1][0]=x2; b[gi*2+1][1]=x3;
            }
            #pragma unroll
            for (int mi = 0; mi < 2; mi++)
                #pragma unroll
                for (int ni = 0; ni < 4; ni++) {
                    MMAH(acc[mi][ni], ah[mi], b[ni][0], b[ni][1]);
                    MMAH(acc[mi][ni], al4[mi], b[ni][0], b[ni][1]);
                }
        }
        __syncwarp();
        if (lane == 0) mbar_arrive(emptyb(s));
    }

    int g = lane >> 2, tg = lane & 3;
    #pragma unroll
    for (int mi = 0; mi < 2; mi++) {
        int row = mbase + warpM * 32 + mi * 16 + g;
        #pragma unroll
        for (int ni = 0; ni < 4; ni++) {
            int col = nb * 128 + warpN * 32 + ni * 8 + tg * 2;
            if (row < cnt)
                *(float2*)(C + (size_t)(r0 + row) * H + col)
                    = make_float2(acc[mi][ni][0], acc[mi][ni][1]);
            if (row + 8 < cnt)
                *(float2*)(C + (size_t)(r0 + row + 8) * H + col)
                    = make_float2(acc[mi][ni][2], acc[mi][ni][3]);
        }
    }
}

// ---------------- combine ---------------------------------------------------
__global__ void __launch_bounds__(256)
combine_kernel(float* __restrict__ Y)
{
    int t = blockIdx.x;
    __shared__ float w[TK];
    __shared__ int   p[TK];
    if (threadIdx.x < TK) {
        w[threadIdx.x] = g_tw[t * TK + threadIdx.x];
        p[threadIdx.x] = g_pos[t * TK + threadIdx.x];
    }
    __syncthreads();
    int c = threadIdx.x * 4;
    float4 acc = *(const float4*)(g_shout + (size_t)t * H + c);
    #pragma unroll
    for (int k = 0; k < TK; k++) {
        float4 v = *(const float4*)(g_outs + (size_t)p[k] * H + c);
        acc.x += w[k] * v.x; acc.y += w[k] * v.y;
        acc.z += w[k] * v.z; acc.w += w[k] * v.w;
    }
    *(float4*)(Y + (size_t)t * H + c) = acc;
}

__global__ void fill_zero(float* p, long long n) {
    long long i = (long long)blockIdx.x * 256 + threadIdx.x;
    if (i < n) p[i] = 0.f;
}

// ---------------- launch -----------------------------------------------------
extern "C" void kernel_launch(void* const* d_in, const int* in_sizes, int n_in,
                              void* d_out, int out_size)
{
    const float* x   = (const float*)d_in[0];
    const float* gw  = (const float*)d_in[1];
    const float* eb  = (const float*)d_in[2];
    const float* wg  = (const float*)d_in[3];
    const float* wu  = (const float*)d_in[4];
    const float* wd  = (const float*)d_in[5];
    const float* wsg = (const float*)d_in[6];
    const float* wsu = (const float*)d_in[7];
    const float* wsd = (const float*)d_in[8];
    float* out = (float*)d_out;

    int T = in_sizes[0] / H;
    int N = T * TK;
    int MT = (T + 127) / 128;

    long long oL = (long long)T * H;
    long long oK = oL + (long long)T * NE;
    long long oEnd = oK + (long long)T * TK;

    float* outLogits = ((long long)out_size >= oK)   ? (out + oL) : nullptr;
    float* outTopkF  = ((long long)out_size >= oEnd) ? (out + oK) : nullptr;
    long long written = ((long long)out_size >= oEnd) ? oEnd
                       : ((long long)out_size >= oK) ? oK
                       : oL;

    cudaFuncSetAttribute(mma_gateup, cudaFuncAttributeMaxDynamicSharedMemorySize, SMEM_GU);
    cudaFuncSetAttribute(mma_down,   cudaFuncAttributeMaxDynamicSharedMemorySize, SMEM_DN);

    init_kernel<<<80, 256>>>();
    gate_kernel<<<T, 128>>>(x, gw, eb, outLogits, outTopkF);
    scan_kernel<<<1, 1>>>();
    scatter_kernel<<<(N + 255) / 256, 256>>>(N);
    gather_x<<<dim3(KC_GU, NT_X, 2), 256>>>(x, T);

    prep_gu<<<dim3(KC_GU, TN_GU, 2 * NE + 2), 256>>>(wg, wu, wsg, wsu);
    prep_dn<<<dim3(KC_DN, TN_DN, NE + 1), 256>>>(wd, wsd);

    mma_gateup<<<dim3(TN_GU, MT, NE + 1), 512, SMEM_GU>>>(T);
    mma_down  <<<dim3(TN_DN, MT, NE + 1), 512, SMEM_DN>>>(T);

    combine_kernel<<<T, 256>>>(out);

    if ((long long)out_size > written) {
        long long rest = (long long)out_size - written;
        fill_zero<<<(unsigned)((rest + 255) / 256), 256>>>(out + written, rest);
    }
}